// round 6
// baseline (speedup 1.0000x reference)
#include <cuda_runtime.h>

#define Bb   2
#define Ss   1024
#define Hh   768
#define Dd   24
#define Kk   96
#define VIN  2304
#define VHID 768

// ---------------- scratch ----------------
__device__ float g_Zj[Bb * Ss * Dd];
__device__ float g_Zi[Bb * Ss * Dd];
__device__ float g_CJ[Bb * Ss * Kk];
__device__ float g_CI[Bb * Ss * Kk];
__device__ float g_probs[(size_t)Bb * Ss * Ss];
__device__ float g_ctx[Bb * Ss * Hh];
__device__ float g_ctxh[Bb * Ss * Hh];
__device__ float g_hid[Bb * Ss * VHID];

__device__ __forceinline__ unsigned long long ffma2(unsigned long long a, unsigned long long b,
                                                    unsigned long long c) {
    unsigned long long d;
    asm("fma.rn.f32x2 %0, %1, %2, %3;" : "=l"(d) : "l"(a), "l"(b), "l"(c));
    return d;
}
__device__ __forceinline__ unsigned long long fpack2(float lo, float hi) {
    unsigned long long d;
    asm("mov.b64 %0, {%1, %2};" : "=l"(d) : "f"(lo), "f"(hi));
    return d;
}
__device__ __forceinline__ float2 funpack2(unsigned long long a) {
    float2 r;
    asm("mov.b64 {%0, %1}, %2;" : "=f"(r.x), "=f"(r.y) : "l"(a));
    return r;
}

// ================= K1: Zj, Zi, cj = b1 + Zj@W1a, ci = Zi@W1b =================
__global__ __launch_bounds__(128) void k1_prep(const float* __restrict__ Hj,
                                               const float* __restrict__ Hi,
                                               const float* __restrict__ Wpj,
                                               const float* __restrict__ Wpi,
                                               const float* __restrict__ W1,
                                               const float* __restrict__ b1) {
    int bs  = blockIdx.x;
    int tid = threadIdx.x;
    int w   = tid >> 5, l = tid & 31;
    __shared__ float part[4][Dd];
    __shared__ float zjs[Dd], zis[Dd];

    const float* Hrow = (w < 2 ? Hj : Hi) + (size_t)bs * Hh;
    const float* Wp   = (w < 2 ? Wpj : Wpi);
    if (l < Dd) {
        float acc = 0.f;
        int h0 = (w & 1) * (Hh / 2);
#pragma unroll 4
        for (int h = h0; h < h0 + Hh / 2; ++h)
            acc = fmaf(Hrow[h], Wp[h * Dd + l], acc);
        part[w][l] = acc;
    }
    __syncthreads();
    if (tid < Dd) {
        float z = part[0][tid] + part[1][tid];
        zjs[tid] = z;
        g_Zj[bs * Dd + tid] = z;
    }
    if (tid >= 32 && tid < 32 + Dd) {
        int d = tid - 32;
        float z = part[2][d] + part[3][d];
        zis[d] = z;
        g_Zi[bs * Dd + d] = z;
    }
    __syncthreads();
    if (tid < Kk) {
        float cj = b1[tid], ci = 0.f;
#pragma unroll
        for (int d = 0; d < Dd; ++d) {
            cj = fmaf(zjs[d], W1[d * Kk + tid], cj);
            ci = fmaf(zis[d], W1[(Dd + d) * Kk + tid], ci);
        }
        g_CJ[bs * Kk + tid] = cj;
        g_CI[bs * Kk + tid] = ci;
    }
}

// ================= K2: pairwise logits + softmax -> probs =================
// 512 threads = 4 groups of 128; group g handles s = blockIdx.x*4 + g.
// Weight tiles shared across groups. Thread handles 1 t-row per iter, 8 iters.
__global__ __launch_bounds__(512) void k2_pair(const float* __restrict__ W1,
                                               const float* __restrict__ W2,
                                               const float* __restrict__ mask) {
    const int tid = threadIdx.x;
    const int g   = tid >> 7;     // group 0..3
    const int lt  = tid & 127;    // lane within group
    const int s0  = blockIdx.x * 4;
    const int s   = s0 + g;
    const int b   = s >> 10;

    __shared__ __align__(16) float w1c_t[Kk][Dd];
    __shared__ __align__(16) float w1d_t[Kk][Dd];
    __shared__ float w2s[Kk];
    __shared__ float cjs[4][Kk];
    __shared__ float zjs[4][Dd];
    __shared__ float lg[4][Ss];
    __shared__ float red[4][4];

    for (int idx = tid; idx < Kk * Dd; idx += 512) {
        int k = idx / Dd, d = idx - k * Dd;
        w1c_t[k][d] = W1[(2 * Dd + d) * Kk + k];
        w1d_t[k][d] = W1[(3 * Dd + d) * Kk + k];
    }
    if (tid < Kk) w2s[tid] = W2[tid];
    if (tid < 4 * Kk) {
        int gg = tid / Kk, k = tid - gg * Kk;
        cjs[gg][k] = g_CJ[(size_t)(s0 + gg) * Kk + k];
    }
    if (tid < 4 * Dd) {
        int gg = tid / Dd, d = tid - gg * Dd;
        zjs[gg][d] = g_Zj[(size_t)(s0 + gg) * Dd + d];
    }
    __syncthreads();

    float zj[Dd];
#pragma unroll
    for (int d = 0; d < Dd; ++d) zj[d] = zjs[g][d];

    const float* ciBase = g_CI + (size_t)b * Ss * Kk;
    const float* ziBase = g_Zi + (size_t)b * Ss * Dd;
    const float* cjRow  = &cjs[g][0];

#pragma unroll 1
    for (int it = 0; it < 8; ++it) {
        int t = it * 128 + lt;

        float zi[Dd];
        {
            const float4* rz = (const float4*)(ziBase + (size_t)t * Dd);
#pragma unroll
            for (int q = 0; q < Dd / 4; ++q) {
                float4 v = rz[q];
                zi[4 * q] = v.x; zi[4 * q + 1] = v.y; zi[4 * q + 2] = v.z; zi[4 * q + 3] = v.w;
            }
        }
        unsigned long long pr[Dd / 2], ad[Dd / 2];
#pragma unroll
        for (int q = 0; q < Dd / 2; ++q) {
            float j0 = zj[2 * q], j1 = zj[2 * q + 1];
            pr[q] = fpack2(j0 * zi[2 * q], j1 * zi[2 * q + 1]);
            ad[q] = fpack2(fabsf(j0 - zi[2 * q]), fabsf(j1 - zi[2 * q + 1]));
        }

        const float* ciRow = ciBase + (size_t)t * Kk;
        float logit = 0.f;

#pragma unroll 1
        for (int k4 = 0; k4 < Kk; k4 += 4) {
            float4 c4 = *(const float4*)(ciRow + k4);
            float cv[4] = {c4.x, c4.y, c4.z, c4.w};
#pragma unroll
            for (int j = 0; j < 4; ++j) {
                int k = k4 + j;
                const ulonglong2* wc = (const ulonglong2*)(&w1c_t[k][0]);
                const ulonglong2* wd = (const ulonglong2*)(&w1d_t[k][0]);
                unsigned long long sP = 0ull, sD = 0ull;  // 2 independent chains
#pragma unroll
                for (int u = 0; u < 6; ++u) {
                    ulonglong2 cW = wc[u];
                    sP = ffma2(pr[2 * u], cW.x, sP);
                    sP = ffma2(pr[2 * u + 1], cW.y, sP);
                    ulonglong2 dW = wd[u];
                    sD = ffma2(ad[2 * u], dW.x, sD);
                    sD = ffma2(ad[2 * u + 1], dW.y, sD);
                }
                float2 uP = funpack2(sP);
                float2 uD = funpack2(sD);
                float h = ((uP.x + uP.y) + (uD.x + uD.y)) + (cjRow[k] + cv[j]);
                h = fmaxf(h, 0.f);
                logit = fmaf(h, w2s[k], logit);
            }
        }
        float m = mask[b * Ss + t];
        lg[g][t] = logit + (1.0f - m) * (-3.402823466e38f);
    }
    __syncthreads();

    // per-group softmax over lg[g][0..1023] (b2 constant -> cancels)
    float mx = -3.402823466e38f;
    for (int i = lt; i < Ss; i += 128) mx = fmaxf(mx, lg[g][i]);
#pragma unroll
    for (int o = 16; o; o >>= 1) mx = fmaxf(mx, __shfl_xor_sync(0xffffffffu, mx, o));
    if ((lt & 31) == 0) red[g][lt >> 5] = mx;
    __syncthreads();
    mx = fmaxf(fmaxf(red[g][0], red[g][1]), fmaxf(red[g][2], red[g][3]));
    __syncthreads();

    float sum = 0.f;
    for (int i = lt; i < Ss; i += 128) {
        float e = __expf(lg[g][i] - mx);
        lg[g][i] = e;
        sum += e;
    }
#pragma unroll
    for (int o = 16; o; o >>= 1) sum += __shfl_xor_sync(0xffffffffu, sum, o);
    if ((lt & 31) == 0) red[g][lt >> 5] = sum;
    __syncthreads();
    sum = (red[g][0] + red[g][1]) + (red[g][2] + red[g][3]);
    float inv = 1.0f / sum;

    float* orow = g_probs + (size_t)s * Ss;
    for (int i = lt; i < Ss; i += 128) orow[i] = lg[g][i] * inv;
}

// ====== GEMM: 128x96 tile, 256 thr, micro 4 row-pairs x 6 cols, k-slab 8, 2 blocks/SM ======
// MODE 0: ctx = probs @ H_i (per b); epilogue also writes ctxh = ctx * Hj
// MODE 1: hid = relu([ctx|Hj|ctxh] @ Wv1 + bv1)
// MODE 2: out = alpha * (hid @ Wv2 + bv2)
template <int MODE>
__global__ __launch_bounds__(256, 2) void gemm_kernel(const float* __restrict__ Ap,
                                                      const float* __restrict__ Bp,
                                                      const float* __restrict__ Hjp,
                                                      const float* __restrict__ bias,
                                                      const float* __restrict__ alpha,
                                                      float* __restrict__ Cp, int Kdim, int lda) {
    const int m0 = blockIdx.x * 128;
    const int n0 = blockIdx.y * 96;
    const float* A = Ap;
    const float* Bm = Bp;
    float* C = Cp;
    size_t rowbase = 0;
    if (MODE == 0) {
        int b = blockIdx.z;
        A += (size_t)b * Ss * Ss;
        Bm += (size_t)b * Ss * Hh;
        C += (size_t)b * Ss * Hh;
        rowbase = (size_t)b * Ss;
    }

    // As2[kk][m2]: f32x2 of rows (2*m2, 2*m2+1). 65-pad: conflict-free LDS.64.
    __shared__ unsigned long long As2[2][8][65];          // 8.3 KB
    // Bs2[kk][n]: (b,b) duplicated. Row stride 98*8=784B = 16B multiple -> LDS.128 aligned.
    __shared__ __align__(16) unsigned long long Bs2[2][8][98];  // 12.5 KB

    const int tid = threadIdx.x;
    const int mg = tid & 15;        // row-pair group
    const int ng = tid >> 4;        // col group (6 cols)
    const int ar = tid >> 1;        // A row 0..127
    const int ac = (tid & 1) * 4;   // A k-offset 0 or 4
    const bool bload = (tid < 192);
    const int b0r = tid / 24, b0c = (tid % 24) * 4;

    unsigned long long acc[4][6];
#pragma unroll
    for (int q = 0; q < 4; ++q)
#pragma unroll
        for (int j = 0; j < 6; ++j) acc[q][j] = 0ull;

    const int nkt = Kdim / 8;

    float4 pa0, pb0;

    auto loadAB = [&](int k0) {
        int kc = k0 + ac;
        if (MODE == 1) {
            int seg = kc / Hh;  // uniform within slab (Hh % 8 == 0)
            const float* base = (seg == 0) ? g_ctx : (seg == 1) ? Hjp : g_ctxh;
            int kq = kc - seg * Hh;
            pa0 = *(const float4*)(base + (size_t)(m0 + ar) * Hh + kq);
        } else {
            pa0 = *(const float4*)(A + (size_t)(m0 + ar) * lda + kc);
        }
        if (bload) pb0 = *(const float4*)(Bm + (size_t)(k0 + b0r) * Hh + n0 + b0c);
    };

    auto storeAB = [&](int buf) {
        float* ap = (float*)&As2[buf][0][0];
        const float va[4] = {pa0.x, pa0.y, pa0.z, pa0.w};
#pragma unroll
        for (int j = 0; j < 4; ++j) ap[(ac + j) * 130 + ar] = va[j];
        if (bload) {
            unsigned long long* bp = &Bs2[buf][0][0];
            const float w0[4] = {pb0.x, pb0.y, pb0.z, pb0.w};
#pragma unroll
            for (int j = 0; j < 4; ++j) bp[b0r * 98 + b0c + j] = fpack2(w0[j], w0[j]);
        }
    };

    loadAB(0);
    storeAB(0);
    __syncthreads();

#pragma unroll 1
    for (int kt = 0; kt < nkt; ++kt) {
        const int cur = kt & 1;
        const bool more = (kt + 1 < nkt);
        if (more) loadAB((kt + 1) * 8);
#pragma unroll
        for (int kk = 0; kk < 8; ++kk) {
            unsigned long long a0 = As2[cur][kk][mg];
            unsigned long long a1 = As2[cur][kk][mg + 16];
            unsigned long long a2 = As2[cur][kk][mg + 32];
            unsigned long long a3 = As2[cur][kk][mg + 48];
            const ulonglong2* bq = (const ulonglong2*)(&Bs2[cur][kk][ng * 6]);
            ulonglong2 b01 = bq[0], b23 = bq[1], b45 = bq[2];
            acc[0][0] = ffma2(a0, b01.x, acc[0][0]);
            acc[0][1] = ffma2(a0, b01.y, acc[0][1]);
            acc[0][2] = ffma2(a0, b23.x, acc[0][2]);
            acc[0][3] = ffma2(a0, b23.y, acc[0][3]);
            acc[0][4] = ffma2(a0, b45.x, acc[0][4]);
            acc[0][5] = ffma2(a0, b45.y, acc[0][5]);
            acc[1][0] = ffma2(a1, b01.x, acc[1][0]);
            acc[1][1] = ffma2(a1, b01.y, acc[1][1]);
            acc[1][2] = ffma2(a1, b23.x, acc[1][2]);
            acc[1][3] = ffma2(a1, b23.y, acc[1][3]);
            acc[1][4] = ffma2(a1, b45.x, acc[1][4]);
            acc[1][5] = ffma2(a1, b45.y, acc[1][5]);
            acc[2][0] = ffma2(a2, b01.x, acc[2][0]);
            acc[2][1] = ffma2(a2, b01.y, acc[2][1]);
            acc[2][2] = ffma2(a2, b23.x, acc[2][2]);
            acc[2][3] = ffma2(a2, b23.y, acc[2][3]);
            acc[2][4] = ffma2(a2, b45.x, acc[2][4]);
            acc[2][5] = ffma2(a2, b45.y, acc[2][5]);
            acc[3][0] = ffma2(a3, b01.x, acc[3][0]);
            acc[3][1] = ffma2(a3, b01.y, acc[3][1]);
            acc[3][2] = ffma2(a3, b23.x, acc[3][2]);
            acc[3][3] = ffma2(a3, b23.y, acc[3][3]);
            acc[3][4] = ffma2(a3, b45.x, acc[3][4]);
            acc[3][5] = ffma2(a3, b45.y, acc[3][5]);
        }
        if (more) {
            storeAB(cur ^ 1);   // safe: writes buffer last READ before previous sync
            __syncthreads();
        }
    }

    // ---------------- epilogue ----------------
    const int col = n0 + ng * 6;
    float bs6[6];
    if (MODE != 0) {
#pragma unroll
        for (int j = 0; j < 6; ++j) bs6[j] = bias[col + j];
    }
    float al = (MODE == 2) ? alpha[0] : 0.f;

#pragma unroll
    for (int q = 0; q < 4; ++q) {
        int r = m0 + 2 * (mg + 16 * q);  // rows r, r+1
        float lo[6], hi[6];
#pragma unroll
        for (int j = 0; j < 6; ++j) {
            float2 u = funpack2(acc[q][j]);
            lo[j] = u.x;
            hi[j] = u.y;
        }
        if (MODE == 0) {
            size_t g0r = rowbase + r, g1r = g0r + 1;
#pragma unroll
            for (int j = 0; j < 6; ++j) {
                C[(size_t)r * Hh + col + j]       = lo[j];
                C[(size_t)(r + 1) * Hh + col + j] = hi[j];
                float h0 = Hjp[g0r * Hh + col + j];
                float h1 = Hjp[g1r * Hh + col + j];
                g_ctxh[g0r * Hh + col + j] = lo[j] * h0;
                g_ctxh[g1r * Hh + col + j] = hi[j] * h1;
            }
        } else if (MODE == 1) {
#pragma unroll
            for (int j = 0; j < 6; ++j) {
                C[(size_t)r * VHID + col + j]       = fmaxf(lo[j] + bs6[j], 0.f);
                C[(size_t)(r + 1) * VHID + col + j] = fmaxf(hi[j] + bs6[j], 0.f);
            }
        } else {
#pragma unroll
            for (int j = 0; j < 6; ++j) {
                C[(size_t)r * Hh + col + j]       = al * (lo[j] + bs6[j]);
                C[(size_t)(r + 1) * Hh + col + j] = al * (hi[j] + bs6[j]);
            }
        }
    }
}

// ================= launch =================
extern "C" void kernel_launch(void* const* d_in, const int* in_sizes, int n_in, void* d_out,
                              int out_size) {
    const float* Hj   = (const float*)d_in[0];
    const float* Hi   = (const float*)d_in[1];
    const float* mask = (const float*)d_in[2];
    const float* Wpj  = (const float*)d_in[3];
    const float* Wpi  = (const float*)d_in[4];
    const float* W1   = (const float*)d_in[5];
    const float* b1   = (const float*)d_in[6];
    const float* W2   = (const float*)d_in[7];
    // d_in[8] = b2: constant logit shift -> cancels in softmax
    const float* Wv1   = (const float*)d_in[9];
    const float* bv1   = (const float*)d_in[10];
    const float* Wv2   = (const float*)d_in[11];
    const float* bv2   = (const float*)d_in[12];
    const float* alpha = (const float*)d_in[13];
    float* out = (float*)d_out;

    float* d_probs = nullptr;
    float* d_ctx = nullptr;
    float* d_hid = nullptr;
    cudaGetSymbolAddress((void**)&d_probs, g_probs);
    cudaGetSymbolAddress((void**)&d_ctx, g_ctx);
    cudaGetSymbolAddress((void**)&d_hid, g_hid);

    k1_prep<<<Bb * Ss, 128>>>(Hj, Hi, Wpj, Wpi, W1, b1);
    k2_pair<<<Bb * Ss / 4, 512>>>(W1, W2, mask);
    gemm_kernel<0><<<dim3(Ss / 128, Hh / 96, Bb), 256>>>(d_probs, Hi, Hj, nullptr, nullptr,
                                                         d_ctx, Ss, Ss);
    gemm_kernel<1><<<dim3(Bb * Ss / 128, VHID / 96), 256>>>(nullptr, Wv1, Hj, bv1, nullptr, d_hid,
                                                            VIN, 0);
    gemm_kernel<2><<<dim3(Bb * Ss / 128, Hh / 96), 256>>>(d_hid, Wv2, nullptr, bv2, alpha, out,
                                                          VHID, VHID);
}

// round 7
// speedup vs baseline: 1.2620x; 1.2620x over previous
#include <cuda_runtime.h>

#define Bb   2
#define Ss   1024
#define Hh   768
#define Dd   24
#define Kk   96
#define VIN  2304
#define VHID 768

// ---------------- scratch ----------------
__device__ float g_Zj[Bb * Ss * Dd];
__device__ float g_Zi[Bb * Ss * Dd];
__device__ float g_CJ[Bb * Ss * Kk];
__device__ float g_CI[Bb * Ss * Kk];
__device__ float g_probs[(size_t)Bb * Ss * Ss];
__device__ float g_ctx[Bb * Ss * Hh];
__device__ float g_ctxh[Bb * Ss * Hh];
__device__ float g_hid[Bb * Ss * VHID];

__device__ __forceinline__ unsigned long long ffma2(unsigned long long a, unsigned long long b,
                                                    unsigned long long c) {
    unsigned long long d;
    asm("fma.rn.f32x2 %0, %1, %2, %3;" : "=l"(d) : "l"(a), "l"(b), "l"(c));
    return d;
}
__device__ __forceinline__ unsigned long long fpack2(float lo, float hi) {
    unsigned long long d;
    asm("mov.b64 %0, {%1, %2};" : "=l"(d) : "f"(lo), "f"(hi));
    return d;
}
__device__ __forceinline__ float2 funpack2(unsigned long long a) {
    float2 r;
    asm("mov.b64 {%0, %1}, %2;" : "=f"(r.x), "=f"(r.y) : "l"(a));
    return r;
}

// ================= K1: Zj, Zi, cj = b1 + Zj@W1a, ci = Zi@W1b =================
__global__ __launch_bounds__(128) void k1_prep(const float* __restrict__ Hj,
                                               const float* __restrict__ Hi,
                                               const float* __restrict__ Wpj,
                                               const float* __restrict__ Wpi,
                                               const float* __restrict__ W1,
                                               const float* __restrict__ b1) {
    int bs  = blockIdx.x;
    int tid = threadIdx.x;
    int w   = tid >> 5, l = tid & 31;
    __shared__ float part[4][Dd];
    __shared__ float zjs[Dd], zis[Dd];

    const float* Hrow = (w < 2 ? Hj : Hi) + (size_t)bs * Hh;
    const float* Wp   = (w < 2 ? Wpj : Wpi);
    if (l < Dd) {
        float acc = 0.f;
        int h0 = (w & 1) * (Hh / 2);
#pragma unroll 4
        for (int h = h0; h < h0 + Hh / 2; ++h)
            acc = fmaf(Hrow[h], Wp[h * Dd + l], acc);
        part[w][l] = acc;
    }
    __syncthreads();
    if (tid < Dd) {
        float z = part[0][tid] + part[1][tid];
        zjs[tid] = z;
        g_Zj[bs * Dd + tid] = z;
    }
    if (tid >= 32 && tid < 32 + Dd) {
        int d = tid - 32;
        float z = part[2][d] + part[3][d];
        zis[d] = z;
        g_Zi[bs * Dd + d] = z;
    }
    __syncthreads();
    if (tid < Kk) {
        float cj = b1[tid], ci = 0.f;
#pragma unroll
        for (int d = 0; d < Dd; ++d) {
            cj = fmaf(zjs[d], W1[d * Kk + tid], cj);
            ci = fmaf(zis[d], W1[(Dd + d) * Kk + tid], ci);
        }
        g_CJ[bs * Kk + tid] = cj;
        g_CI[bs * Kk + tid] = ci;
    }
}

// ================= K2: pairwise logits + softmax -> probs (R5 version) =================
__global__ __launch_bounds__(128) void k2_pair(const float* __restrict__ W1,
                                               const float* __restrict__ W2,
                                               const float* __restrict__ mask) {
    int bs  = blockIdx.x;
    int b   = bs >> 10;
    int tid = threadIdx.x;

    __shared__ __align__(16) float w1c_t[Kk][Dd];
    __shared__ __align__(16) float w1d_t[Kk][Dd];
    __shared__ float w2s[Kk], cjs[Kk], zjs[Dd];
    __shared__ float lg[Ss];
    __shared__ float red[4];

    for (int idx = tid; idx < Kk * Dd; idx += 128) {
        int k = idx / Dd, d = idx - k * Dd;
        w1c_t[k][d] = W1[(2 * Dd + d) * Kk + k];
        w1d_t[k][d] = W1[(3 * Dd + d) * Kk + k];
    }
    if (tid < Kk) {
        w2s[tid] = W2[tid];
        cjs[tid] = g_CJ[bs * Kk + tid];
    }
    if (tid < Dd) zjs[tid] = g_Zj[bs * Dd + tid];
    __syncthreads();

    float zj[Dd];
#pragma unroll
    for (int d = 0; d < Dd; ++d) zj[d] = zjs[d];

    const float* ciBase = g_CI + (size_t)b * Ss * Kk;
    const float* ziBase = g_Zi + (size_t)b * Ss * Dd;

#pragma unroll 1
    for (int it = 0; it < 4; ++it) {
        int ta = it * 256 + tid * 2;
        int tb = ta + 1;

        float zA[Dd], zB[Dd];
        {
            const float4* ra = (const float4*)(ziBase + (size_t)ta * Dd);
            const float4* rb = (const float4*)(ziBase + (size_t)tb * Dd);
#pragma unroll
            for (int q = 0; q < Dd / 4; ++q) {
                float4 va = ra[q], vb = rb[q];
                zA[4 * q] = va.x; zA[4 * q + 1] = va.y; zA[4 * q + 2] = va.z; zA[4 * q + 3] = va.w;
                zB[4 * q] = vb.x; zB[4 * q + 1] = vb.y; zB[4 * q + 2] = vb.z; zB[4 * q + 3] = vb.w;
            }
        }
        unsigned long long pa[Dd / 2], aa[Dd / 2], pb[Dd / 2], ab[Dd / 2];
#pragma unroll
        for (int q = 0; q < Dd / 2; ++q) {
            float j0 = zj[2 * q], j1 = zj[2 * q + 1];
            pa[q] = fpack2(j0 * zA[2 * q], j1 * zA[2 * q + 1]);
            aa[q] = fpack2(fabsf(j0 - zA[2 * q]), fabsf(j1 - zA[2 * q + 1]));
            pb[q] = fpack2(j0 * zB[2 * q], j1 * zB[2 * q + 1]);
            ab[q] = fpack2(fabsf(j0 - zB[2 * q]), fabsf(j1 - zB[2 * q + 1]));
        }

        const float* ciA = ciBase + (size_t)ta * Kk;
        const float* ciB = ciBase + (size_t)tb * Kk;
        float logitA = 0.f, logitB = 0.f;

#pragma unroll 1
        for (int k4 = 0; k4 < Kk; k4 += 4) {
            float4 cA4 = *(const float4*)(ciA + k4);
            float4 cB4 = *(const float4*)(ciB + k4);
            float cAv[4] = {cA4.x, cA4.y, cA4.z, cA4.w};
            float cBv[4] = {cB4.x, cB4.y, cB4.z, cB4.w};
#pragma unroll
            for (int j = 0; j < 4; ++j) {
                int k = k4 + j;
                const ulonglong2* wc = (const ulonglong2*)(&w1c_t[k][0]);
                const ulonglong2* wd = (const ulonglong2*)(&w1d_t[k][0]);
                unsigned long long sA = 0ull, sB = 0ull;
#pragma unroll
                for (int u = 0; u < 6; ++u) {
                    ulonglong2 c = wc[u];
                    sA = ffma2(pa[2 * u], c.x, sA);
                    sA = ffma2(pa[2 * u + 1], c.y, sA);
                    sB = ffma2(pb[2 * u], c.x, sB);
                    sB = ffma2(pb[2 * u + 1], c.y, sB);
                }
#pragma unroll
                for (int u = 0; u < 6; ++u) {
                    ulonglong2 c = wd[u];
                    sA = ffma2(aa[2 * u], c.x, sA);
                    sA = ffma2(aa[2 * u + 1], c.y, sA);
                    sB = ffma2(ab[2 * u], c.x, sB);
                    sB = ffma2(ab[2 * u + 1], c.y, sB);
                }
                float2 uA = funpack2(sA);
                float2 uB = funpack2(sB);
                float hA = (uA.x + uA.y) + (cjs[k] + cAv[j]);
                float hB = (uB.x + uB.y) + (cjs[k] + cBv[j]);
                hA = fmaxf(hA, 0.f);
                hB = fmaxf(hB, 0.f);
                logitA = fmaf(hA, w2s[k], logitA);
                logitB = fmaf(hB, w2s[k], logitB);
            }
        }
        float mA = mask[b * Ss + ta];
        float mB = mask[b * Ss + tb];
        lg[ta] = logitA + (1.0f - mA) * (-3.402823466e38f);
        lg[tb] = logitB + (1.0f - mB) * (-3.402823466e38f);
    }
    __syncthreads();

    float mx = -3.402823466e38f;
    for (int i = tid; i < Ss; i += 128) mx = fmaxf(mx, lg[i]);
#pragma unroll
    for (int o = 16; o; o >>= 1) mx = fmaxf(mx, __shfl_xor_sync(0xffffffffu, mx, o));
    if ((tid & 31) == 0) red[tid >> 5] = mx;
    __syncthreads();
    mx = fmaxf(fmaxf(red[0], red[1]), fmaxf(red[2], red[3]));
    __syncthreads();

    float sum = 0.f;
    for (int i = tid; i < Ss; i += 128) {
        float e = __expf(lg[i] - mx);
        lg[i] = e;
        sum += e;
    }
#pragma unroll
    for (int o = 16; o; o >>= 1) sum += __shfl_xor_sync(0xffffffffu, sum, o);
    if ((tid & 31) == 0) red[tid >> 5] = sum;
    __syncthreads();
    sum = (red[0] + red[1]) + (red[2] + red[3]);
    float inv = 1.0f / sum;

    float* orow = g_probs + (size_t)bs * Ss;
    for (int i = tid; i < Ss; i += 128) orow[i] = lg[i] * inv;
}

// ====== GEMM: 128x96 tile, 512 thr (16 warps/SM), micro 2 row-pairs x 6 cols, k-slab 16 ======
// MODE 0: ctx = probs @ H_i (per b); epilogue also writes ctxh = ctx * Hj
// MODE 1: hid = relu([ctx|Hj|ctxh] @ Wv1 + bv1)
// MODE 2: out = alpha * (hid @ Wv2 + bv2)
template <int MODE>
__global__ __launch_bounds__(512, 1) void gemm_kernel(const float* __restrict__ Ap,
                                                      const float* __restrict__ Bp,
                                                      const float* __restrict__ Hjp,
                                                      const float* __restrict__ bias,
                                                      const float* __restrict__ alpha,
                                                      float* __restrict__ Cp, int Kdim, int lda) {
    const int m0 = blockIdx.x * 128;
    const int n0 = blockIdx.y * 96;
    const float* A = Ap;
    const float* Bm = Bp;
    float* C = Cp;
    size_t rowbase = 0;
    if (MODE == 0) {
        int b = blockIdx.z;
        A += (size_t)b * Ss * Ss;
        Bm += (size_t)b * Ss * Hh;
        C += (size_t)b * Ss * Hh;
        rowbase = (size_t)b * Ss;
    }

    // As2[kk][m2]: f32x2 of rows (2*m2, 2*m2+1). 65-pad: LDS.64 conflict-free.
    __shared__ unsigned long long As2[2][16][65];               // 16.6 KB
    // Bs2[kk][n]: (b,b) dup. Row stride 98*8 = 784B (16B mult) -> LDS.128 aligned; broadcast reads.
    __shared__ __align__(16) unsigned long long Bs2[2][16][98]; // 25.1 KB

    const int tid = threadIdx.x;
    const int mg = tid & 31;        // row-pair group: pairs mg and mg+32
    const int ng = tid >> 5;        // warp-uniform col group: cols ng*6 .. +5
    const int ar = tid >> 2;        // A row 0..127
    const int ac = (tid & 3) * 4;   // A k-offset {0,4,8,12}
    const bool bload = (tid < 384);
    const int b0r = tid / 24, b0c = (tid % 24) * 4;

    unsigned long long acc[2][6];
#pragma unroll
    for (int q = 0; q < 2; ++q)
#pragma unroll
        for (int j = 0; j < 6; ++j) acc[q][j] = 0ull;

    const int nkt = Kdim / 16;

    float4 pa0, pb0;

    auto loadAB = [&](int k0) {
        int kc = k0 + ac;
        if (MODE == 1) {
            int seg = kc / Hh;  // uniform within slab (Hh % 16 == 0)
            const float* base = (seg == 0) ? g_ctx : (seg == 1) ? Hjp : g_ctxh;
            int kq = kc - seg * Hh;
            pa0 = *(const float4*)(base + (size_t)(m0 + ar) * Hh + kq);
        } else {
            pa0 = *(const float4*)(A + (size_t)(m0 + ar) * lda + kc);
        }
        if (bload) pb0 = *(const float4*)(Bm + (size_t)(k0 + b0r) * Hh + n0 + b0c);
    };

    auto storeAB = [&](int buf) {
        float* ap = (float*)&As2[buf][0][0];
        const float va[4] = {pa0.x, pa0.y, pa0.z, pa0.w};
#pragma unroll
        for (int j = 0; j < 4; ++j) ap[(ac + j) * 130 + ar] = va[j];
        if (bload) {
            unsigned long long* bp = &Bs2[buf][0][0];
            const float w0[4] = {pb0.x, pb0.y, pb0.z, pb0.w};
#pragma unroll
            for (int j = 0; j < 4; ++j) bp[b0r * 98 + b0c + j] = fpack2(w0[j], w0[j]);
        }
    };

    loadAB(0);
    storeAB(0);
    __syncthreads();

#pragma unroll 1
    for (int kt = 0; kt < nkt; ++kt) {
        const int cur = kt & 1;
        const bool more = (kt + 1 < nkt);
        if (more) loadAB((kt + 1) * 16);
#pragma unroll
        for (int kk = 0; kk < 16; ++kk) {
            unsigned long long a0 = As2[cur][kk][mg];
            unsigned long long a1 = As2[cur][kk][mg + 32];
            const ulonglong2* bq = (const ulonglong2*)(&Bs2[cur][kk][ng * 6]);
            ulonglong2 b01 = bq[0], b23 = bq[1], b45 = bq[2];
            acc[0][0] = ffma2(a0, b01.x, acc[0][0]);
            acc[0][1] = ffma2(a0, b01.y, acc[0][1]);
            acc[0][2] = ffma2(a0, b23.x, acc[0][2]);
            acc[0][3] = ffma2(a0, b23.y, acc[0][3]);
            acc[0][4] = ffma2(a0, b45.x, acc[0][4]);
            acc[0][5] = ffma2(a0, b45.y, acc[0][5]);
            acc[1][0] = ffma2(a1, b01.x, acc[1][0]);
            acc[1][1] = ffma2(a1, b01.y, acc[1][1]);
            acc[1][2] = ffma2(a1, b23.x, acc[1][2]);
            acc[1][3] = ffma2(a1, b23.y, acc[1][3]);
            acc[1][4] = ffma2(a1, b45.x, acc[1][4]);
            acc[1][5] = ffma2(a1, b45.y, acc[1][5]);
        }
        if (more) {
            storeAB(cur ^ 1);   // writes buffer last READ before previous sync
            __syncthreads();
        }
    }

    // ---------------- epilogue ----------------
    const int col = n0 + ng * 6;
    float bs6[6];
    if (MODE != 0) {
#pragma unroll
        for (int j = 0; j < 6; ++j) bs6[j] = bias[col + j];
    }
    float al = (MODE == 2) ? alpha[0] : 0.f;

#pragma unroll
    for (int q = 0; q < 2; ++q) {
        int r = m0 + 2 * (mg + 32 * q);  // rows r, r+1
        float lo[6], hi[6];
#pragma unroll
        for (int j = 0; j < 6; ++j) {
            float2 u = funpack2(acc[q][j]);
            lo[j] = u.x;
            hi[j] = u.y;
        }
        if (MODE == 0) {
            size_t g0r = rowbase + r, g1r = g0r + 1;
#pragma unroll
            for (int j = 0; j < 6; ++j) {
                C[(size_t)r * Hh + col + j]       = lo[j];
                C[(size_t)(r + 1) * Hh + col + j] = hi[j];
                float h0 = Hjp[g0r * Hh + col + j];
                float h1 = Hjp[g1r * Hh + col + j];
                g_ctxh[g0r * Hh + col + j] = lo[j] * h0;
                g_ctxh[g1r * Hh + col + j] = hi[j] * h1;
            }
        } else if (MODE == 1) {
#pragma unroll
            for (int j = 0; j < 6; ++j) {
                C[(size_t)r * VHID + col + j]       = fmaxf(lo[j] + bs6[j], 0.f);
                C[(size_t)(r + 1) * VHID + col + j] = fmaxf(hi[j] + bs6[j], 0.f);
            }
        } else {
#pragma unroll
            for (int j = 0; j < 6; ++j) {
                C[(size_t)r * Hh + col + j]       = al * (lo[j] + bs6[j]);
                C[(size_t)(r + 1) * Hh + col + j] = al * (hi[j] + bs6[j]);
            }
        }
    }
}

// ================= launch =================
extern "C" void kernel_launch(void* const* d_in, const int* in_sizes, int n_in, void* d_out,
                              int out_size) {
    const float* Hj   = (const float*)d_in[0];
    const float* Hi   = (const float*)d_in[1];
    const float* mask = (const float*)d_in[2];
    const float* Wpj  = (const float*)d_in[3];
    const float* Wpi  = (const float*)d_in[4];
    const float* W1   = (const float*)d_in[5];
    const float* b1   = (const float*)d_in[6];
    const float* W2   = (const float*)d_in[7];
    // d_in[8] = b2: constant logit shift -> cancels in softmax
    const float* Wv1   = (const float*)d_in[9];
    const float* bv1   = (const float*)d_in[10];
    const float* Wv2   = (const float*)d_in[11];
    const float* bv2   = (const float*)d_in[12];
    const float* alpha = (const float*)d_in[13];
    float* out = (float*)d_out;

    float* d_probs = nullptr;
    float* d_ctx = nullptr;
    float* d_hid = nullptr;
    cudaGetSymbolAddress((void**)&d_probs, g_probs);
    cudaGetSymbolAddress((void**)&d_ctx, g_ctx);
    cudaGetSymbolAddress((void**)&d_hid, g_hid);

    k1_prep<<<Bb * Ss, 128>>>(Hj, Hi, Wpj, Wpi, W1, b1);
    k2_pair<<<Bb * Ss, 128>>>(W1, W2, mask);
    gemm_kernel<0><<<dim3(Ss / 128, Hh / 96, Bb), 512>>>(d_probs, Hi, Hj, nullptr, nullptr,
                                                         d_ctx, Ss, Ss);
    gemm_kernel<1><<<dim3(Bb * Ss / 128, VHID / 96), 512>>>(nullptr, Wv1, Hj, bv1, nullptr, d_hid,
                                                            VIN, 0);
    gemm_kernel<2><<<dim3(Bb * Ss / 128, Hh / 96), 512>>>(d_hid, Wv2, nullptr, bv2, alpha, out,
                                                          VHID, VHID);
}

// round 8
// speedup vs baseline: 1.3770x; 1.0912x over previous
#include <cuda_runtime.h>

#define Bb   2
#define Ss   1024
#define Hh   768
#define Dd   24
#define Kk   96
#define VIN  2304
#define VHID 768

// ---------------- scratch ----------------
__device__ float g_Zj[Bb * Ss * Dd];
__device__ float g_Zi[Bb * Ss * Dd];
__device__ float g_CJ[Bb * Ss * Kk];
__device__ float g_CI[Bb * Ss * Kk];
__device__ float g_probs[(size_t)Bb * Ss * Ss];
__device__ float g_ctx[Bb * Ss * Hh];
__device__ float g_ctxh[Bb * Ss * Hh];
__device__ float g_hid[Bb * Ss * VHID];

__device__ __forceinline__ unsigned long long ffma2(unsigned long long a, unsigned long long b,
                                                    unsigned long long c) {
    unsigned long long d;
    asm("fma.rn.f32x2 %0, %1, %2, %3;" : "=l"(d) : "l"(a), "l"(b), "l"(c));
    return d;
}
__device__ __forceinline__ unsigned long long fadd2(unsigned long long a, unsigned long long b) {
    unsigned long long d;
    asm("add.rn.f32x2 %0, %1, %2;" : "=l"(d) : "l"(a), "l"(b));
    return d;
}
__device__ __forceinline__ unsigned long long fpack2(float lo, float hi) {
    unsigned long long d;
    asm("mov.b64 %0, {%1, %2};" : "=l"(d) : "f"(lo), "f"(hi));
    return d;
}
__device__ __forceinline__ float2 funpack2(unsigned long long a) {
    float2 r;
    asm("mov.b64 {%0, %1}, %2;" : "=f"(r.x), "=f"(r.y) : "l"(a));
    return r;
}

// ================= K1: Zj, Zi, cj = b1 + Zj@W1a, ci = Zi@W1b =================
__global__ __launch_bounds__(128) void k1_prep(const float* __restrict__ Hj,
                                               const float* __restrict__ Hi,
                                               const float* __restrict__ Wpj,
                                               const float* __restrict__ Wpi,
                                               const float* __restrict__ W1,
                                               const float* __restrict__ b1) {
    int bs  = blockIdx.x;
    int tid = threadIdx.x;
    int w   = tid >> 5, l = tid & 31;
    __shared__ float part[4][Dd];
    __shared__ float zjs[Dd], zis[Dd];

    const float* Hrow = (w < 2 ? Hj : Hi) + (size_t)bs * Hh;
    const float* Wp   = (w < 2 ? Wpj : Wpi);
    if (l < Dd) {
        float acc = 0.f;
        int h0 = (w & 1) * (Hh / 2);
#pragma unroll 4
        for (int h = h0; h < h0 + Hh / 2; ++h)
            acc = fmaf(Hrow[h], Wp[h * Dd + l], acc);
        part[w][l] = acc;
    }
    __syncthreads();
    if (tid < Dd) {
        float z = part[0][tid] + part[1][tid];
        zjs[tid] = z;
        g_Zj[bs * Dd + tid] = z;
    }
    if (tid >= 32 && tid < 32 + Dd) {
        int d = tid - 32;
        float z = part[2][d] + part[3][d];
        zis[d] = z;
        g_Zi[bs * Dd + d] = z;
    }
    __syncthreads();
    if (tid < Kk) {
        float cj = b1[tid], ci = 0.f;
#pragma unroll
        for (int d = 0; d < Dd; ++d) {
            cj = fmaf(zjs[d], W1[d * Kk + tid], cj);
            ci = fmaf(zis[d], W1[(Dd + d) * Kk + tid], ci);
        }
        g_CJ[bs * Kk + tid] = cj;
        g_CI[bs * Kk + tid] = ci;
    }
}

// ================= K2: pairwise logits + softmax -> probs =================
// 128 thr/block, 1 s-row per block, 2 t-rows per thread, 4 independent FFMA2 chains.
__global__ __launch_bounds__(128) void k2_pair(const float* __restrict__ W1,
                                               const float* __restrict__ W2,
                                               const float* __restrict__ mask) {
    int bs  = blockIdx.x;
    int b   = bs >> 10;
    int tid = threadIdx.x;

    __shared__ __align__(16) float w1c_t[Kk][Dd];
    __shared__ __align__(16) float w1d_t[Kk][Dd];
    __shared__ float w2s[Kk], cjs[Kk], zjs[Dd];
    __shared__ float lg[Ss];
    __shared__ float red[4];

    for (int idx = tid; idx < Kk * Dd; idx += 128) {
        int k = idx / Dd, d = idx - k * Dd;
        w1c_t[k][d] = W1[(2 * Dd + d) * Kk + k];
        w1d_t[k][d] = W1[(3 * Dd + d) * Kk + k];
    }
    if (tid < Kk) {
        w2s[tid] = W2[tid];
        cjs[tid] = g_CJ[bs * Kk + tid];
    }
    if (tid < Dd) zjs[tid] = g_Zj[bs * Dd + tid];
    __syncthreads();

    float zj[Dd];
#pragma unroll
    for (int d = 0; d < Dd; ++d) zj[d] = zjs[d];

    const float* ciBase = g_CI + (size_t)b * Ss * Kk;
    const float* ziBase = g_Zi + (size_t)b * Ss * Dd;

#pragma unroll 1
    for (int it = 0; it < 4; ++it) {
        int ta = it * 256 + tid * 2;
        int tb = ta + 1;

        float zA[Dd], zB[Dd];
        {
            const float4* ra = (const float4*)(ziBase + (size_t)ta * Dd);
            const float4* rb = (const float4*)(ziBase + (size_t)tb * Dd);
#pragma unroll
            for (int q = 0; q < Dd / 4; ++q) {
                float4 va = ra[q], vb = rb[q];
                zA[4 * q] = va.x; zA[4 * q + 1] = va.y; zA[4 * q + 2] = va.z; zA[4 * q + 3] = va.w;
                zB[4 * q] = vb.x; zB[4 * q + 1] = vb.y; zB[4 * q + 2] = vb.z; zB[4 * q + 3] = vb.w;
            }
        }
        unsigned long long pa[Dd / 2], aa[Dd / 2], pb[Dd / 2], ab[Dd / 2];
#pragma unroll
        for (int q = 0; q < Dd / 2; ++q) {
            float j0 = zj[2 * q], j1 = zj[2 * q + 1];
            pa[q] = fpack2(j0 * zA[2 * q], j1 * zA[2 * q + 1]);
            aa[q] = fpack2(fabsf(j0 - zA[2 * q]), fabsf(j1 - zA[2 * q + 1]));
            pb[q] = fpack2(j0 * zB[2 * q], j1 * zB[2 * q + 1]);
            ab[q] = fpack2(fabsf(j0 - zB[2 * q]), fabsf(j1 - zB[2 * q + 1]));
        }

        const float* ciA = ciBase + (size_t)ta * Kk;
        const float* ciB = ciBase + (size_t)tb * Kk;
        float logitA = 0.f, logitB = 0.f;

#pragma unroll 1
        for (int k4 = 0; k4 < Kk; k4 += 4) {
            float4 cA4 = *(const float4*)(ciA + k4);
            float4 cB4 = *(const float4*)(ciB + k4);
            float cAv[4] = {cA4.x, cA4.y, cA4.z, cA4.w};
            float cBv[4] = {cB4.x, cB4.y, cB4.z, cB4.w};
#pragma unroll
            for (int j = 0; j < 4; ++j) {
                int k = k4 + j;
                const ulonglong2* wc = (const ulonglong2*)(&w1c_t[k][0]);
                const ulonglong2* wd = (const ulonglong2*)(&w1d_t[k][0]);
                // 4 independent chains, each touched every 4th FFMA2 (dist 4 >= lat 4)
                unsigned long long sAp = 0ull, sAd = 0ull, sBp = 0ull, sBd = 0ull;
#pragma unroll
                for (int u = 0; u < 6; ++u) {
                    ulonglong2 c = wc[u];
                    ulonglong2 dd = wd[u];
                    sAp = ffma2(pa[2 * u], c.x, sAp);
                    sBp = ffma2(pb[2 * u], c.x, sBp);
                    sAd = ffma2(aa[2 * u], dd.x, sAd);
                    sBd = ffma2(ab[2 * u], dd.x, sBd);
                    sAp = ffma2(pa[2 * u + 1], c.y, sAp);
                    sBp = ffma2(pb[2 * u + 1], c.y, sBp);
                    sAd = ffma2(aa[2 * u + 1], dd.y, sAd);
                    sBd = ffma2(ab[2 * u + 1], dd.y, sBd);
                }
                float2 uA = funpack2(fadd2(sAp, sAd));
                float2 uB = funpack2(fadd2(sBp, sBd));
                float hA = (uA.x + uA.y) + (cjs[k] + cAv[j]);
                float hB = (uB.x + uB.y) + (cjs[k] + cBv[j]);
                hA = fmaxf(hA, 0.f);
                hB = fmaxf(hB, 0.f);
                logitA = fmaf(hA, w2s[k], logitA);
                logitB = fmaf(hB, w2s[k], logitB);
            }
        }
        float mA = mask[b * Ss + ta];
        float mB = mask[b * Ss + tb];
        lg[ta] = logitA + (1.0f - mA) * (-3.402823466e38f);
        lg[tb] = logitB + (1.0f - mB) * (-3.402823466e38f);
    }
    __syncthreads();

    float mx = -3.402823466e38f;
    for (int i = tid; i < Ss; i += 128) mx = fmaxf(mx, lg[i]);
#pragma unroll
    for (int o = 16; o; o >>= 1) mx = fmaxf(mx, __shfl_xor_sync(0xffffffffu, mx, o));
    if ((tid & 31) == 0) red[tid >> 5] = mx;
    __syncthreads();
    mx = fmaxf(fmaxf(red[0], red[1]), fmaxf(red[2], red[3]));
    __syncthreads();

    float sum = 0.f;
    for (int i = tid; i < Ss; i += 128) {
        float e = __expf(lg[i] - mx);
        lg[i] = e;
        sum += e;
    }
#pragma unroll
    for (int o = 16; o; o >>= 1) sum += __shfl_xor_sync(0xffffffffu, sum, o);
    if ((tid & 31) == 0) red[tid >> 5] = sum;
    __syncthreads();
    sum = (red[0] + red[1]) + (red[2] + red[3]);
    float inv = 1.0f / sum;

    float* orow = g_probs + (size_t)bs * Ss;
    for (int i = tid; i < Ss; i += 128) orow[i] = lg[i] * inv;
}

// ====== GEMM (R5 measured-best): 128x96 tile, 256 thr, micro 4 row-pairs x 6, k-slab 16 ======
// MODE 0: ctx = probs @ H_i (per b); epilogue also writes ctxh = ctx * Hj
// MODE 1: hid = relu([ctx|Hj|ctxh] @ Wv1 + bv1)
// MODE 2: out = alpha * (hid @ Wv2 + bv2)
template <int MODE>
__global__ __launch_bounds__(256) void gemm_kernel(const float* __restrict__ Ap,
                                                   const float* __restrict__ Bp,
                                                   const float* __restrict__ Hjp,
                                                   const float* __restrict__ bias,
                                                   const float* __restrict__ alpha,
                                                   float* __restrict__ Cp, int Kdim, int lda) {
    const int m0 = blockIdx.x * 128;
    const int n0 = blockIdx.y * 96;
    const float* A = Ap;
    const float* Bm = Bp;
    float* C = Cp;
    size_t rowbase = 0;
    if (MODE == 0) {
        int b = blockIdx.z;
        A += (size_t)b * Ss * Ss;
        Bm += (size_t)b * Ss * Hh;
        C += (size_t)b * Ss * Hh;
        rowbase = (size_t)b * Ss;
    }

    __shared__ unsigned long long As2[2][16][65];
    __shared__ __align__(16) unsigned long long Bs2[2][16][98];

    const int tid = threadIdx.x;
    const int mg = tid & 15;
    const int ng = tid >> 4;
    const int ar0 = tid >> 2, ar1 = ar0 + 64;
    const int ac  = (tid & 3) * 4;
    const int b0r = tid / 24, b0c = (tid % 24) * 4;
    const int i1  = tid + 256;
    const int b1r = i1 / 24, b1c = (i1 % 24) * 4;
    const bool hasB1 = (tid < 128);

    unsigned long long acc[4][6];
#pragma unroll
    for (int q = 0; q < 4; ++q)
#pragma unroll
        for (int j = 0; j < 6; ++j) acc[q][j] = 0ull;

    const int nkt = Kdim / 16;

    float4 pa0, pa1, pb0, pb1;

    auto loadAB = [&](int k0) {
        int kc = k0 + ac;
        if (MODE == 1) {
            int seg = kc / Hh;
            const float* base = (seg == 0) ? g_ctx : (seg == 1) ? Hjp : g_ctxh;
            int kq = kc - seg * Hh;
            pa0 = *(const float4*)(base + (size_t)(m0 + ar0) * Hh + kq);
            pa1 = *(const float4*)(base + (size_t)(m0 + ar1) * Hh + kq);
        } else {
            pa0 = *(const float4*)(A + (size_t)(m0 + ar0) * lda + kc);
            pa1 = *(const float4*)(A + (size_t)(m0 + ar1) * lda + kc);
        }
        pb0 = *(const float4*)(Bm + (size_t)(k0 + b0r) * Hh + n0 + b0c);
        if (hasB1) pb1 = *(const float4*)(Bm + (size_t)(k0 + b1r) * Hh + n0 + b1c);
    };

    auto storeAB = [&](int buf) {
        float* ap = (float*)&As2[buf][0][0];
        const float va[4] = {pa0.x, pa0.y, pa0.z, pa0.w};
        const float vb[4] = {pa1.x, pa1.y, pa1.z, pa1.w};
#pragma unroll
        for (int j = 0; j < 4; ++j) {
            ap[(ac + j) * 130 + ar0] = va[j];
            ap[(ac + j) * 130 + ar1] = vb[j];
        }
        unsigned long long* bp = &Bs2[buf][0][0];
        const float w0[4] = {pb0.x, pb0.y, pb0.z, pb0.w};
#pragma unroll
        for (int j = 0; j < 4; ++j) bp[b0r * 98 + b0c + j] = fpack2(w0[j], w0[j]);
        if (hasB1) {
            const float w1[4] = {pb1.x, pb1.y, pb1.z, pb1.w};
#pragma unroll
            for (int j = 0; j < 4; ++j) bp[b1r * 98 + b1c + j] = fpack2(w1[j], w1[j]);
        }
    };

    loadAB(0);
    storeAB(0);
    __syncthreads();

#pragma unroll 1
    for (int kt = 0; kt < nkt; ++kt) {
        const int cur = kt & 1;
        const bool more = (kt + 1 < nkt);
        if (more) loadAB((kt + 1) * 16);
#pragma unroll
        for (int kk = 0; kk < 16; ++kk) {
            unsigned long long a0 = As2[cur][kk][mg];
            unsigned long long a1 = As2[cur][kk][mg + 16];
            unsigned long long a2 = As2[cur][kk][mg + 32];
            unsigned long long a3 = As2[cur][kk][mg + 48];
            const ulonglong2* bq = (const ulonglong2*)(&Bs2[cur][kk][ng * 6]);
            ulonglong2 b01 = bq[0], b23 = bq[1], b45 = bq[2];
            acc[0][0] = ffma2(a0, b01.x, acc[0][0]);
            acc[0][1] = ffma2(a0, b01.y, acc[0][1]);
            acc[0][2] = ffma2(a0, b23.x, acc[0][2]);
            acc[0][3] = ffma2(a0, b23.y, acc[0][3]);
            acc[0][4] = ffma2(a0, b45.x, acc[0][4]);
            acc[0][5] = ffma2(a0, b45.y, acc[0][5]);
            acc[1][0] = ffma2(a1, b01.x, acc[1][0]);
            acc[1][1] = ffma2(a1, b01.y, acc[1][1]);
            acc[1][2] = ffma2(a1, b23.x, acc[1][2]);
            acc[1][3] = ffma2(a1, b23.y, acc[1][3]);
            acc[1][4] = ffma2(a1, b45.x, acc[1][4]);
            acc[1][5] = ffma2(a1, b45.y, acc[1][5]);
            acc[2][0] = ffma2(a2, b01.x, acc[2][0]);
            acc[2][1] = ffma2(a2, b01.y, acc[2][1]);
            acc[2][2] = ffma2(a2, b23.x, acc[2][2]);
            acc[2][3] = ffma2(a2, b23.y, acc[2][3]);
            acc[2][4] = ffma2(a2, b45.x, acc[2][4]);
            acc[2][5] = ffma2(a2, b45.y, acc[2][5]);
            acc[3][0] = ffma2(a3, b01.x, acc[3][0]);
            acc[3][1] = ffma2(a3, b01.y, acc[3][1]);
            acc[3][2] = ffma2(a3, b23.x, acc[3][2]);
            acc[3][3] = ffma2(a3, b23.y, acc[3][3]);
            acc[3][4] = ffma2(a3, b45.x, acc[3][4]);
            acc[3][5] = ffma2(a3, b45.y, acc[3][5]);
        }
        if (more) {
            storeAB(cur ^ 1);
            __syncthreads();
        }
    }

    const int col = n0 + ng * 6;
    float bs6[6];
    if (MODE != 0) {
#pragma unroll
        for (int j = 0; j < 6; ++j) bs6[j] = bias[col + j];
    }
    float al = (MODE == 2) ? alpha[0] : 0.f;

#pragma unroll
    for (int q = 0; q < 4; ++q) {
        int r = m0 + 2 * (mg + 16 * q);
        float lo[6], hi[6];
#pragma unroll
        for (int j = 0; j < 6; ++j) {
            float2 u = funpack2(acc[q][j]);
            lo[j] = u.x;
            hi[j] = u.y;
        }
        if (MODE == 0) {
            size_t g0r = rowbase + r, g1r = g0r + 1;
#pragma unroll
            for (int j = 0; j < 6; ++j) {
                C[(size_t)r * Hh + col + j]       = lo[j];
                C[(size_t)(r + 1) * Hh + col + j] = hi[j];
                float h0 = Hjp[g0r * Hh + col + j];
                float h1 = Hjp[g1r * Hh + col + j];
                g_ctxh[g0r * Hh + col + j] = lo[j] * h0;
                g_ctxh[g1r * Hh + col + j] = hi[j] * h1;
            }
        } else if (MODE == 1) {
#pragma unroll
            for (int j = 0; j < 6; ++j) {
                C[(size_t)r * VHID + col + j]       = fmaxf(lo[j] + bs6[j], 0.f);
                C[(size_t)(r + 1) * VHID + col + j] = fmaxf(hi[j] + bs6[j], 0.f);
            }
        } else {
#pragma unroll
            for (int j = 0; j < 6; ++j) {
                C[(size_t)r * Hh + col + j]       = al * (lo[j] + bs6[j]);
                C[(size_t)(r + 1) * Hh + col + j] = al * (hi[j] + bs6[j]);
            }
        }
    }
}

// ================= launch =================
extern "C" void kernel_launch(void* const* d_in, const int* in_sizes, int n_in, void* d_out,
                              int out_size) {
    const float* Hj   = (const float*)d_in[0];
    const float* Hi   = (const float*)d_in[1];
    const float* mask = (const float*)d_in[2];
    const float* Wpj  = (const float*)d_in[3];
    const float* Wpi  = (const float*)d_in[4];
    const float* W1   = (const float*)d_in[5];
    const float* b1   = (const float*)d_in[6];
    const float* W2   = (const float*)d_in[7];
    // d_in[8] = b2: constant logit shift -> cancels in softmax
    const float* Wv1   = (const float*)d_in[9];
    const float* bv1   = (const float*)d_in[10];
    const float* Wv2   = (const float*)d_in[11];
    const float* bv2   = (const float*)d_in[12];
    const float* alpha = (const float*)d_in[13];
    float* out = (float*)d_out;

    float* d_probs = nullptr;
    float* d_ctx = nullptr;
    float* d_hid = nullptr;
    cudaGetSymbolAddress((void**)&d_probs, g_probs);
    cudaGetSymbolAddress((void**)&d_ctx, g_ctx);
    cudaGetSymbolAddress((void**)&d_hid, g_hid);

    k1_prep<<<Bb * Ss, 128>>>(Hj, Hi, Wpj, Wpi, W1, b1);
    k2_pair<<<Bb * Ss, 128>>>(W1, W2, mask);
    gemm_kernel<0><<<dim3(Ss / 128, Hh / 96, Bb), 256>>>(d_probs, Hi, Hj, nullptr, nullptr,
                                                         d_ctx, Ss, Ss);
    gemm_kernel<1><<<dim3(Bb * Ss / 128, VHID / 96), 256>>>(nullptr, Wv1, Hj, bv1, nullptr, d_hid,
                                                            VIN, 0);
    gemm_kernel<2><<<dim3(Bb * Ss / 128, Hh / 96), 256>>>(d_hid, Wv2, nullptr, bv2, alpha, out,
                                                          VHID, VHID);
}

// round 9
// speedup vs baseline: 1.7844x; 1.2958x over previous
#include <cuda_runtime.h>

#define Bb   2
#define Ss   1024
#define Hh   768
#define Dd   24
#define Kk   96
#define VIN  2304
#define VHID 768

// ---------------- scratch ----------------
__device__ float g_Zj[Bb * Ss * Dd];
__device__ float g_Zi[Bb * Ss * Dd];
__device__ float g_CJ[Bb * Ss * Kk];
__device__ float g_CI[Bb * Ss * Kk];
__device__ float g_probs[(size_t)Bb * Ss * Ss];
__device__ float g_ctx[Bb * Ss * Hh];
__device__ float g_ctxh[Bb * Ss * Hh];
__device__ float g_hid[Bb * Ss * VHID];

__device__ __forceinline__ unsigned long long ffma2(unsigned long long a, unsigned long long b,
                                                    unsigned long long c) {
    unsigned long long d;
    asm("fma.rn.f32x2 %0, %1, %2, %3;" : "=l"(d) : "l"(a), "l"(b), "l"(c));
    return d;
}
__device__ __forceinline__ unsigned long long fadd2(unsigned long long a, unsigned long long b) {
    unsigned long long d;
    asm("add.rn.f32x2 %0, %1, %2;" : "=l"(d) : "l"(a), "l"(b));
    return d;
}
__device__ __forceinline__ unsigned long long fpack2(float lo, float hi) {
    unsigned long long d;
    asm("mov.b64 %0, {%1, %2};" : "=l"(d) : "f"(lo), "f"(hi));
    return d;
}
__device__ __forceinline__ float2 funpack2(unsigned long long a) {
    float2 r;
    asm("mov.b64 {%0, %1}, %2;" : "=f"(r.x), "=f"(r.y) : "l"(a));
    return r;
}
__device__ __forceinline__ unsigned tf32r(float x) {
    unsigned r;
    asm("cvt.rna.tf32.f32 %0, %1;" : "=r"(r) : "f"(x));
    return r;
}
__device__ __forceinline__ void mma_tf32(float& d0, float& d1, float& d2, float& d3,
                                         unsigned a0, unsigned a1, unsigned a2, unsigned a3,
                                         unsigned b0, unsigned b1) {
    asm volatile(
        "mma.sync.aligned.m16n8k8.row.col.f32.tf32.tf32.f32 "
        "{%0,%1,%2,%3}, {%4,%5,%6,%7}, {%8,%9}, {%0,%1,%2,%3};"
        : "+f"(d0), "+f"(d1), "+f"(d2), "+f"(d3)
        : "r"(a0), "r"(a1), "r"(a2), "r"(a3), "r"(b0), "r"(b1));
}

// ================= K1: Zj, Zi, cj = b1 + Zj@W1a, ci = Zi@W1b =================
__global__ __launch_bounds__(128) void k1_prep(const float* __restrict__ Hj,
                                               const float* __restrict__ Hi,
                                               const float* __restrict__ Wpj,
                                               const float* __restrict__ Wpi,
                                               const float* __restrict__ W1,
                                               const float* __restrict__ b1) {
    int bs  = blockIdx.x;
    int tid = threadIdx.x;
    int w   = tid >> 5, l = tid & 31;
    __shared__ float part[4][Dd];
    __shared__ float zjs[Dd], zis[Dd];

    const float* Hrow = (w < 2 ? Hj : Hi) + (size_t)bs * Hh;
    const float* Wp   = (w < 2 ? Wpj : Wpi);
    if (l < Dd) {
        float acc = 0.f;
        int h0 = (w & 1) * (Hh / 2);
#pragma unroll 4
        for (int h = h0; h < h0 + Hh / 2; ++h)
            acc = fmaf(Hrow[h], Wp[h * Dd + l], acc);
        part[w][l] = acc;
    }
    __syncthreads();
    if (tid < Dd) {
        float z = part[0][tid] + part[1][tid];
        zjs[tid] = z;
        g_Zj[bs * Dd + tid] = z;
    }
    if (tid >= 32 && tid < 32 + Dd) {
        int d = tid - 32;
        float z = part[2][d] + part[3][d];
        zis[d] = z;
        g_Zi[bs * Dd + d] = z;
    }
    __syncthreads();
    if (tid < Kk) {
        float cj = b1[tid], ci = 0.f;
#pragma unroll
        for (int d = 0; d < Dd; ++d) {
            cj = fmaf(zjs[d], W1[d * Kk + tid], cj);
            ci = fmaf(zis[d], W1[(Dd + d) * Kk + tid], ci);
        }
        g_CJ[bs * Kk + tid] = cj;
        g_CI[bs * Kk + tid] = ci;
    }
}

// ================= K2: pairwise logits + softmax -> probs (measured-stable) =================
__global__ __launch_bounds__(128) void k2_pair(const float* __restrict__ W1,
                                               const float* __restrict__ W2,
                                               const float* __restrict__ mask) {
    int bs  = blockIdx.x;
    int b   = bs >> 10;
    int tid = threadIdx.x;

    __shared__ __align__(16) float w1c_t[Kk][Dd];
    __shared__ __align__(16) float w1d_t[Kk][Dd];
    __shared__ float w2s[Kk], cjs[Kk], zjs[Dd];
    __shared__ float lg[Ss];
    __shared__ float red[4];

    for (int idx = tid; idx < Kk * Dd; idx += 128) {
        int k = idx / Dd, d = idx - k * Dd;
        w1c_t[k][d] = W1[(2 * Dd + d) * Kk + k];
        w1d_t[k][d] = W1[(3 * Dd + d) * Kk + k];
    }
    if (tid < Kk) {
        w2s[tid] = W2[tid];
        cjs[tid] = g_CJ[bs * Kk + tid];
    }
    if (tid < Dd) zjs[tid] = g_Zj[bs * Dd + tid];
    __syncthreads();

    float zj[Dd];
#pragma unroll
    for (int d = 0; d < Dd; ++d) zj[d] = zjs[d];

    const float* ciBase = g_CI + (size_t)b * Ss * Kk;
    const float* ziBase = g_Zi + (size_t)b * Ss * Dd;

#pragma unroll 1
    for (int it = 0; it < 4; ++it) {
        int ta = it * 256 + tid * 2;
        int tb = ta + 1;

        float zA[Dd], zB[Dd];
        {
            const float4* ra = (const float4*)(ziBase + (size_t)ta * Dd);
            const float4* rb = (const float4*)(ziBase + (size_t)tb * Dd);
#pragma unroll
            for (int q = 0; q < Dd / 4; ++q) {
                float4 va = ra[q], vb = rb[q];
                zA[4 * q] = va.x; zA[4 * q + 1] = va.y; zA[4 * q + 2] = va.z; zA[4 * q + 3] = va.w;
                zB[4 * q] = vb.x; zB[4 * q + 1] = vb.y; zB[4 * q + 2] = vb.z; zB[4 * q + 3] = vb.w;
            }
        }
        unsigned long long pa[Dd / 2], aa[Dd / 2], pb[Dd / 2], ab[Dd / 2];
#pragma unroll
        for (int q = 0; q < Dd / 2; ++q) {
            float j0 = zj[2 * q], j1 = zj[2 * q + 1];
            pa[q] = fpack2(j0 * zA[2 * q], j1 * zA[2 * q + 1]);
            aa[q] = fpack2(fabsf(j0 - zA[2 * q]), fabsf(j1 - zA[2 * q + 1]));
            pb[q] = fpack2(j0 * zB[2 * q], j1 * zB[2 * q + 1]);
            ab[q] = fpack2(fabsf(j0 - zB[2 * q]), fabsf(j1 - zB[2 * q + 1]));
        }

        const float* ciA = ciBase + (size_t)ta * Kk;
        const float* ciB = ciBase + (size_t)tb * Kk;
        float logitA = 0.f, logitB = 0.f;

#pragma unroll 1
        for (int k4 = 0; k4 < Kk; k4 += 4) {
            float4 cA4 = *(const float4*)(ciA + k4);
            float4 cB4 = *(const float4*)(ciB + k4);
            float cAv[4] = {cA4.x, cA4.y, cA4.z, cA4.w};
            float cBv[4] = {cB4.x, cB4.y, cB4.z, cB4.w};
#pragma unroll
            for (int j = 0; j < 4; ++j) {
                int k = k4 + j;
                const ulonglong2* wc = (const ulonglong2*)(&w1c_t[k][0]);
                const ulonglong2* wd = (const ulonglong2*)(&w1d_t[k][0]);
                unsigned long long sAp = 0ull, sAd = 0ull, sBp = 0ull, sBd = 0ull;
#pragma unroll
                for (int u = 0; u < 6; ++u) {
                    ulonglong2 c = wc[u];
                    ulonglong2 dd = wd[u];
                    sAp = ffma2(pa[2 * u], c.x, sAp);
                    sBp = ffma2(pb[2 * u], c.x, sBp);
                    sAd = ffma2(aa[2 * u], dd.x, sAd);
                    sBd = ffma2(ab[2 * u], dd.x, sBd);
                    sAp = ffma2(pa[2 * u + 1], c.y, sAp);
                    sBp = ffma2(pb[2 * u + 1], c.y, sBp);
                    sAd = ffma2(aa[2 * u + 1], dd.y, sAd);
                    sBd = ffma2(ab[2 * u + 1], dd.y, sBd);
                }
                float2 uA = funpack2(fadd2(sAp, sAd));
                float2 uB = funpack2(fadd2(sBp, sBd));
                float hA = (uA.x + uA.y) + (cjs[k] + cAv[j]);
                float hB = (uB.x + uB.y) + (cjs[k] + cBv[j]);
                hA = fmaxf(hA, 0.f);
                hB = fmaxf(hB, 0.f);
                logitA = fmaf(hA, w2s[k], logitA);
                logitB = fmaf(hB, w2s[k], logitB);
            }
        }
        float mA = mask[b * Ss + ta];
        float mB = mask[b * Ss + tb];
        lg[ta] = logitA + (1.0f - mA) * (-3.402823466e38f);
        lg[tb] = logitB + (1.0f - mB) * (-3.402823466e38f);
    }
    __syncthreads();

    float mx = -3.402823466e38f;
    for (int i = tid; i < Ss; i += 128) mx = fmaxf(mx, lg[i]);
#pragma unroll
    for (int o = 16; o; o >>= 1) mx = fmaxf(mx, __shfl_xor_sync(0xffffffffu, mx, o));
    if ((tid & 31) == 0) red[tid >> 5] = mx;
    __syncthreads();
    mx = fmaxf(fmaxf(red[0], red[1]), fmaxf(red[2], red[3]));
    __syncthreads();

    float sum = 0.f;
    for (int i = tid; i < Ss; i += 128) {
        float e = __expf(lg[i] - mx);
        lg[i] = e;
        sum += e;
    }
#pragma unroll
    for (int o = 16; o; o >>= 1) sum += __shfl_xor_sync(0xffffffffu, sum, o);
    if ((tid & 31) == 0) red[tid >> 5] = sum;
    __syncthreads();
    sum = (red[0] + red[1]) + (red[2] + red[3]);
    float inv = 1.0f / sum;

    float* orow = g_probs + (size_t)bs * Ss;
    for (int i = tid; i < Ss; i += 128) orow[i] = lg[i] * inv;
}

// ====== tf32 tensor-core GEMM: 128x96 tile, 256 thr = 8 warps (4m x 2n), k-slab 16 ======
// mma.sync.m16n8k8 tf32; per warp 2 m-tiles x 6 n-tiles. Operands RNA-rounded to tf32.
// MODE 0: ctx = probs @ H_i (per b); epilogue also writes ctxh = ctx * Hj
// MODE 1: hid = relu([ctx|Hj|ctxh] @ Wv1 + bv1)
// MODE 2: out = alpha * (hid @ Wv2 + bv2)
template <int MODE>
__global__ __launch_bounds__(256) void gemm_mma(const float* __restrict__ Ap,
                                                const float* __restrict__ Bp,
                                                const float* __restrict__ Hjp,
                                                const float* __restrict__ bias,
                                                const float* __restrict__ alpha,
                                                float* __restrict__ Cp, int Kdim, int lda) {
    const int m0 = blockIdx.x * 128;
    const int n0 = blockIdx.y * 96;
    const float* A = Ap;
    const float* Bm = Bp;
    float* C = Cp;
    size_t rowbase = 0;
    if (MODE == 0) {
        int b = blockIdx.z;
        A += (size_t)b * Ss * Ss;
        Bm += (size_t)b * Ss * Hh;
        C += (size_t)b * Ss * Hh;
        rowbase = (size_t)b * Ss;
    }

    // pad 20: frag-A LDS 20*g + t4 (mod 32) all-distinct -> conflict-free
    __shared__ unsigned As[2][128][20];   // 20.5 KB
    // pad 104: frag-B LDS 8*t4 + g (mod 32) all-distinct -> conflict-free
    __shared__ unsigned Bs[2][16][104];   // 13.3 KB

    const int tid  = threadIdx.x;
    const int warp = tid >> 5, lane = tid & 31;
    const int g  = lane >> 2, t4 = lane & 3;
    const int wm = warp & 3;   // 0..3 -> m offset wm*32
    const int wn = warp >> 2;  // 0..1 -> n offset wn*48

    // A global load: row = tid>>1 (0..127), k-offset = (tid&1)*8, two float4
    const int ar = tid >> 1, ac = (tid & 1) * 8;
    // B global load: 16 x 96 floats = 384 float4; threads 0..255 + first 128 again
    const int b0r = tid / 24, b0c = (tid % 24) * 4;
    const int i1  = tid + 256;
    const int b1r = i1 / 24, b1c = (i1 % 24) * 4;
    const bool hasB1 = (tid < 128);

    float acc[2][6][4];
#pragma unroll
    for (int mt = 0; mt < 2; ++mt)
#pragma unroll
        for (int nt = 0; nt < 6; ++nt)
#pragma unroll
            for (int v = 0; v < 4; ++v) acc[mt][nt][v] = 0.f;

    const int nkt = Kdim / 16;

    float4 pa0, pa1, pb0, pb1;

    auto loadAB = [&](int k0) {
        int kc = k0 + ac;
        if (MODE == 1) {
            int seg = kc / Hh;  // slab-uniform (Hh % 16 == 0)
            const float* base = (seg == 0) ? g_ctx : (seg == 1) ? Hjp : g_ctxh;
            int kq = kc - seg * Hh;
            pa0 = *(const float4*)(base + (size_t)(m0 + ar) * Hh + kq);
            pa1 = *(const float4*)(base + (size_t)(m0 + ar) * Hh + kq + 4);
        } else {
            pa0 = *(const float4*)(A + (size_t)(m0 + ar) * lda + kc);
            pa1 = *(const float4*)(A + (size_t)(m0 + ar) * lda + kc + 4);
        }
        pb0 = *(const float4*)(Bm + (size_t)(k0 + b0r) * Hh + n0 + b0c);
        if (hasB1) pb1 = *(const float4*)(Bm + (size_t)(k0 + b1r) * Hh + n0 + b1c);
    };

    auto storeAB = [&](int buf) {
        const float va[8] = {pa0.x, pa0.y, pa0.z, pa0.w, pa1.x, pa1.y, pa1.z, pa1.w};
#pragma unroll
        for (int j = 0; j < 8; ++j) As[buf][ar][ac + j] = tf32r(va[j]);
        const float w0[4] = {pb0.x, pb0.y, pb0.z, pb0.w};
#pragma unroll
        for (int j = 0; j < 4; ++j) Bs[buf][b0r][b0c + j] = tf32r(w0[j]);
        if (hasB1) {
            const float w1[4] = {pb1.x, pb1.y, pb1.z, pb1.w};
#pragma unroll
            for (int j = 0; j < 4; ++j) Bs[buf][b1r][b1c + j] = tf32r(w1[j]);
        }
    };

    loadAB(0);
    storeAB(0);
    __syncthreads();

#pragma unroll 1
    for (int kt = 0; kt < nkt; ++kt) {
        const int cur = kt & 1;
        const bool more = (kt + 1 < nkt);
        if (more) loadAB((kt + 1) * 16);

#pragma unroll
        for (int k8 = 0; k8 < 16; k8 += 8) {
            unsigned afr[2][4], bfr[6][2];
#pragma unroll
            for (int mt = 0; mt < 2; ++mt) {
                int rb = wm * 32 + mt * 16 + g;
                afr[mt][0] = As[cur][rb][k8 + t4];
                afr[mt][1] = As[cur][rb + 8][k8 + t4];
                afr[mt][2] = As[cur][rb][k8 + t4 + 4];
                afr[mt][3] = As[cur][rb + 8][k8 + t4 + 4];
            }
#pragma unroll
            for (int nt = 0; nt < 6; ++nt) {
                int cb = wn * 48 + nt * 8 + g;
                bfr[nt][0] = Bs[cur][k8 + t4][cb];
                bfr[nt][1] = Bs[cur][k8 + t4 + 4][cb];
            }
#pragma unroll
            for (int mt = 0; mt < 2; ++mt)
#pragma unroll
                for (int nt = 0; nt < 6; ++nt)
                    mma_tf32(acc[mt][nt][0], acc[mt][nt][1], acc[mt][nt][2], acc[mt][nt][3],
                             afr[mt][0], afr[mt][1], afr[mt][2], afr[mt][3],
                             bfr[nt][0], bfr[nt][1]);
        }
        if (more) {
            storeAB(cur ^ 1);   // buffer last read before previous sync
            __syncthreads();
        }
    }

    // ---------------- epilogue ----------------
    const float al = (MODE == 2) ? alpha[0] : 0.f;
#pragma unroll
    for (int mt = 0; mt < 2; ++mt) {
        int r0 = m0 + wm * 32 + mt * 16 + g;
        int r1 = r0 + 8;
#pragma unroll
        for (int nt = 0; nt < 6; ++nt) {
            int c0 = n0 + wn * 48 + nt * 8 + 2 * t4;  // even -> 8B aligned
            float v00 = acc[mt][nt][0], v01 = acc[mt][nt][1];
            float v10 = acc[mt][nt][2], v11 = acc[mt][nt][3];
            if (MODE == 0) {
                *(float2*)(&C[(size_t)r0 * Hh + c0]) = make_float2(v00, v01);
                *(float2*)(&C[(size_t)r1 * Hh + c0]) = make_float2(v10, v11);
                size_t g0 = rowbase + r0, g1 = rowbase + r1;
                float2 h0 = *(const float2*)(Hjp + g0 * Hh + c0);
                float2 h1 = *(const float2*)(Hjp + g1 * Hh + c0);
                *(float2*)(&g_ctxh[g0 * Hh + c0]) = make_float2(v00 * h0.x, v01 * h0.y);
                *(float2*)(&g_ctxh[g1 * Hh + c0]) = make_float2(v10 * h1.x, v11 * h1.y);
            } else if (MODE == 1) {
                float2 bs = *(const float2*)(&bias[c0]);
                *(float2*)(&C[(size_t)r0 * VHID + c0]) =
                    make_float2(fmaxf(v00 + bs.x, 0.f), fmaxf(v01 + bs.y, 0.f));
                *(float2*)(&C[(size_t)r1 * VHID + c0]) =
                    make_float2(fmaxf(v10 + bs.x, 0.f), fmaxf(v11 + bs.y, 0.f));
            } else {
                float2 bs = *(const float2*)(&bias[c0]);
                *(float2*)(&C[(size_t)r0 * Hh + c0]) =
                    make_float2(al * (v00 + bs.x), al * (v01 + bs.y));
                *(float2*)(&C[(size_t)r1 * Hh + c0]) =
                    make_float2(al * (v10 + bs.x), al * (v11 + bs.y));
            }
        }
    }
}

// ================= launch =================
extern "C" void kernel_launch(void* const* d_in, const int* in_sizes, int n_in, void* d_out,
                              int out_size) {
    const float* Hj   = (const float*)d_in[0];
    const float* Hi   = (const float*)d_in[1];
    const float* mask = (const float*)d_in[2];
    const float* Wpj  = (const float*)d_in[3];
    const float* Wpi  = (const float*)d_in[4];
    const float* W1   = (const float*)d_in[5];
    const float* b1   = (const float*)d_in[6];
    const float* W2   = (const float*)d_in[7];
    // d_in[8] = b2: constant logit shift -> cancels in softmax
    const float* Wv1   = (const float*)d_in[9];
    const float* bv1   = (const float*)d_in[10];
    const float* Wv2   = (const float*)d_in[11];
    const float* bv2   = (const float*)d_in[12];
    const float* alpha = (const float*)d_in[13];
    float* out = (float*)d_out;

    float* d_probs = nullptr;
    float* d_ctx = nullptr;
    float* d_hid = nullptr;
    cudaGetSymbolAddress((void**)&d_probs, g_probs);
    cudaGetSymbolAddress((void**)&d_ctx, g_ctx);
    cudaGetSymbolAddress((void**)&d_hid, g_hid);

    k1_prep<<<Bb * Ss, 128>>>(Hj, Hi, Wpj, Wpi, W1, b1);
    k2_pair<<<Bb * Ss, 128>>>(W1, W2, mask);
    gemm_mma<0><<<dim3(Ss / 128, Hh / 96, Bb), 256>>>(d_probs, Hi, Hj, nullptr, nullptr,
                                                      d_ctx, Ss, Ss);
    gemm_mma<1><<<dim3(Bb * Ss / 128, VHID / 96), 256>>>(nullptr, Wv1, Hj, bv1, nullptr, d_hid,
                                                         VIN, 0);
    gemm_mma<2><<<dim3(Bb * Ss / 128, Hh / 96), 256>>>(d_hid, Wv2, nullptr, bv2, alpha, out,
                                                       VHID, VHID);
}

// round 10
// speedup vs baseline: 2.3339x; 1.3080x over previous
#include <cuda_runtime.h>

#define Bb   2
#define Ss   1024
#define Hh   768
#define Dd   24
#define Kk   96
#define VIN  2304
#define VHID 768

// ---------------- scratch ----------------
__device__ float g_Zj[Bb * Ss * Dd];
__device__ float g_Zi[Bb * Ss * Dd];
__device__ float g_CJ[Bb * Ss * Kk];
__device__ float g_CI[Bb * Ss * Kk];
__device__ float g_probs[(size_t)Bb * Ss * Ss];
__device__ float g_ctx[Bb * Ss * Hh];
__device__ float g_ctxh[Bb * Ss * Hh];
__device__ float g_hid[Bb * Ss * VHID];

__device__ __forceinline__ unsigned tf32r(float x) {
    unsigned r;
    asm("cvt.rna.tf32.f32 %0, %1;" : "=r"(r) : "f"(x));
    return r;
}
__device__ __forceinline__ void mma_tf32(float& d0, float& d1, float& d2, float& d3,
                                         unsigned a0, unsigned a1, unsigned a2, unsigned a3,
                                         unsigned b0, unsigned b1) {
    asm volatile(
        "mma.sync.aligned.m16n8k8.row.col.f32.tf32.tf32.f32 "
        "{%0,%1,%2,%3}, {%4,%5,%6,%7}, {%8,%9}, {%0,%1,%2,%3};"
        : "+f"(d0), "+f"(d1), "+f"(d2), "+f"(d3)
        : "r"(a0), "r"(a1), "r"(a2), "r"(a3), "r"(b0), "r"(b1));
}

// ================= K1: Zj, Zi, cj = b1 + Zj@W1a, ci = Zi@W1b =================
__global__ __launch_bounds__(128) void k1_prep(const float* __restrict__ Hj,
                                               const float* __restrict__ Hi,
                                               const float* __restrict__ Wpj,
                                               const float* __restrict__ Wpi,
                                               const float* __restrict__ W1,
                                               const float* __restrict__ b1) {
    int bs  = blockIdx.x;
    int tid = threadIdx.x;
    int w   = tid >> 5, l = tid & 31;
    __shared__ float part[4][Dd];
    __shared__ float zjs[Dd], zis[Dd];

    const float* Hrow = (w < 2 ? Hj : Hi) + (size_t)bs * Hh;
    const float* Wp   = (w < 2 ? Wpj : Wpi);
    if (l < Dd) {
        float acc = 0.f;
        int h0 = (w & 1) * (Hh / 2);
#pragma unroll 4
        for (int h = h0; h < h0 + Hh / 2; ++h)
            acc = fmaf(Hrow[h], Wp[h * Dd + l], acc);
        part[w][l] = acc;
    }
    __syncthreads();
    if (tid < Dd) {
        float z = part[0][tid] + part[1][tid];
        zjs[tid] = z;
        g_Zj[bs * Dd + tid] = z;
    }
    if (tid >= 32 && tid < 32 + Dd) {
        int d = tid - 32;
        float z = part[2][d] + part[3][d];
        zis[d] = z;
        g_Zi[bs * Dd + d] = z;
    }
    __syncthreads();
    if (tid < Kk) {
        float cj = b1[tid], ci = 0.f;
#pragma unroll
        for (int d = 0; d < Dd; ++d) {
            cj = fmaf(zjs[d], W1[d * Kk + tid], cj);
            ci = fmaf(zis[d], W1[(Dd + d) * Kk + tid], ci);
        }
        g_CJ[bs * Kk + tid] = cj;
        g_CI[bs * Kk + tid] = ci;
    }
}

// ================= K2 (tensor-core): logits + softmax per s-row =================
// Block = one (b,s). H[t,96] = F[t,48] @ Wcd[48,96], acc preloaded with ci[t,k]+cj[k].
// 256 thr = 8 warps: wm = warp&1 (2 x 32 rows), wn = warp>>1 (4 x 24 cols).
// 16 sub-tiles of 64 t-rows. K=48 = 6 mma k-steps.
__global__ __launch_bounds__(256) void k2_mma(const float* __restrict__ W1,
                                              const float* __restrict__ W2,
                                              const float* __restrict__ mask) {
    const int bs  = blockIdx.x;
    const int b   = bs >> 10;
    const int tid = threadIdx.x;
    const int warp = tid >> 5, lane = tid & 31;
    const int g  = lane >> 2, t4 = lane & 3;
    const int wm = warp & 1;   // m offset wm*32
    const int wn = warp >> 1;  // n offset wn*24

    __shared__ unsigned Ws[48][104];  // pad 104: B-frag (8*t4+g) mod 32 distinct
    __shared__ unsigned Fs[64][52];   // pad 52:  A-frag (20*g+t4) mod 32 distinct
    __shared__ float cjw[Kk], w2s[Kk], zjs[Dd];
    __shared__ float lg[Ss];
    __shared__ float lgpart[4][64];
    __shared__ float red[8];

    // weights Wcd[d][k]: d<24 -> W1c, d>=24 -> W1d (rows 2*Dd.., 3*Dd.. of W1)
    for (int idx = tid; idx < 48 * Kk; idx += 256) {
        int d = idx / Kk, k = idx - d * Kk;
        float v = (d < Dd) ? W1[(2 * Dd + d) * Kk + k] : W1[(3 * Dd + (d - Dd)) * Kk + k];
        Ws[d][k] = tf32r(v);
    }
    if (tid < Kk) {
        cjw[tid] = g_CJ[(size_t)bs * Kk + tid];
        w2s[tid] = W2[tid];
    }
    if (tid < Dd) zjs[tid] = g_Zj[(size_t)bs * Dd + tid];
    __syncthreads();

    float zj[Dd];
#pragma unroll
    for (int d = 0; d < Dd; ++d) zj[d] = zjs[d];

    const float* ciBase = g_CI + (size_t)b * Ss * Kk;
    const float* ziBase = g_Zi + (size_t)b * Ss * Dd;

#pragma unroll 1
    for (int sub = 0; sub < 16; ++sub) {
        const int t0 = sub * 64;

        // ---- features: thread -> row r = tid>>2, part p = tid&3 ----
        {
            const int r = tid >> 2, p = tid & 3;
            const int t = t0 + r;
            const int half = p & 1;            // d range half*12 .. +11
            const float* zr = ziBase + (size_t)t * Dd + half * 12;
            float zi[12];
#pragma unroll
            for (int q = 0; q < 3; ++q) {
                float4 v = *(const float4*)(zr + 4 * q);
                zi[4 * q] = v.x; zi[4 * q + 1] = v.y; zi[4 * q + 2] = v.z; zi[4 * q + 3] = v.w;
            }
            const int base = half * 12 + ((p >= 2) ? 24 : 0);
            if (p < 2) {
#pragma unroll
                for (int j = 0; j < 12; ++j)
                    Fs[r][base + j] = tf32r(zj[half * 12 + j] * zi[j]);
            } else {
#pragma unroll
                for (int j = 0; j < 12; ++j)
                    Fs[r][base + j] = tf32r(fabsf(zj[half * 12 + j] - zi[j]));
            }
        }
        __syncthreads();

        // ---- acc init with ci + cj ----
        float acc[2][3][4];
#pragma unroll
        for (int mt = 0; mt < 2; ++mt) {
            int r0 = wm * 32 + mt * 16 + g;
            int r1 = r0 + 8;
#pragma unroll
            for (int nt = 0; nt < 3; ++nt) {
                int c = wn * 24 + nt * 8 + 2 * t4;
                float2 ci0 = *(const float2*)(ciBase + (size_t)(t0 + r0) * Kk + c);
                float2 ci1 = *(const float2*)(ciBase + (size_t)(t0 + r1) * Kk + c);
                acc[mt][nt][0] = ci0.x + cjw[c];
                acc[mt][nt][1] = ci0.y + cjw[c + 1];
                acc[mt][nt][2] = ci1.x + cjw[c];
                acc[mt][nt][3] = ci1.y + cjw[c + 1];
            }
        }

        // ---- mma: K = 48, 6 k-steps ----
#pragma unroll
        for (int k8 = 0; k8 < 48; k8 += 8) {
            unsigned afr[2][4], bfr[3][2];
#pragma unroll
            for (int mt = 0; mt < 2; ++mt) {
                int rb = wm * 32 + mt * 16 + g;
                afr[mt][0] = Fs[rb][k8 + t4];
                afr[mt][1] = Fs[rb + 8][k8 + t4];
                afr[mt][2] = Fs[rb][k8 + t4 + 4];
                afr[mt][3] = Fs[rb + 8][k8 + t4 + 4];
            }
#pragma unroll
            for (int nt = 0; nt < 3; ++nt) {
                int cb = wn * 24 + nt * 8 + g;
                bfr[nt][0] = Ws[k8 + t4][cb];
                bfr[nt][1] = Ws[k8 + t4 + 4][cb];
            }
#pragma unroll
            for (int mt = 0; mt < 2; ++mt)
#pragma unroll
                for (int nt = 0; nt < 3; ++nt)
                    mma_tf32(acc[mt][nt][0], acc[mt][nt][1], acc[mt][nt][2], acc[mt][nt][3],
                             afr[mt][0], afr[mt][1], afr[mt][2], afr[mt][3],
                             bfr[nt][0], bfr[nt][1]);
        }

        // ---- epilogue: relu + w2-dot, reduce over t4 then over wn ----
#pragma unroll
        for (int mt = 0; mt < 2; ++mt) {
            float p0 = 0.f, p1 = 0.f;
#pragma unroll
            for (int nt = 0; nt < 3; ++nt) {
                int c = wn * 24 + nt * 8 + 2 * t4;
                float wa = w2s[c], wb = w2s[c + 1];
                p0 = fmaf(fmaxf(acc[mt][nt][0], 0.f), wa, p0);
                p0 = fmaf(fmaxf(acc[mt][nt][1], 0.f), wb, p0);
                p1 = fmaf(fmaxf(acc[mt][nt][2], 0.f), wa, p1);
                p1 = fmaf(fmaxf(acc[mt][nt][3], 0.f), wb, p1);
            }
            p0 += __shfl_xor_sync(0xffffffffu, p0, 1);
            p0 += __shfl_xor_sync(0xffffffffu, p0, 2);
            p1 += __shfl_xor_sync(0xffffffffu, p1, 1);
            p1 += __shfl_xor_sync(0xffffffffu, p1, 2);
            if (t4 == 0) {
                lgpart[wn][wm * 32 + mt * 16 + g]     = p0;
                lgpart[wn][wm * 32 + mt * 16 + g + 8] = p1;
            }
        }
        __syncthreads();
        if (tid < 64) {
            float v = (lgpart[0][tid] + lgpart[1][tid]) + (lgpart[2][tid] + lgpart[3][tid]);
            int t = t0 + tid;
            float m = mask[b * Ss + t];
            lg[t] = v + (1.0f - m) * (-3.402823466e38f);
        }
        __syncthreads();  // protects Fs/lgpart before next sub-tile
    }

    // ---- softmax over lg[0..1023] (b2 constant -> cancels) ----
    float mx = -3.402823466e38f;
    for (int i = tid; i < Ss; i += 256) mx = fmaxf(mx, lg[i]);
#pragma unroll
    for (int o = 16; o; o >>= 1) mx = fmaxf(mx, __shfl_xor_sync(0xffffffffu, mx, o));
    if (lane == 0) red[warp] = mx;
    __syncthreads();
    mx = red[0];
#pragma unroll
    for (int w2i = 1; w2i < 8; ++w2i) mx = fmaxf(mx, red[w2i]);
    __syncthreads();

    float sum = 0.f;
    for (int i = tid; i < Ss; i += 256) {
        float e = __expf(lg[i] - mx);
        lg[i] = e;
        sum += e;
    }
#pragma unroll
    for (int o = 16; o; o >>= 1) sum += __shfl_xor_sync(0xffffffffu, sum, o);
    if (lane == 0) red[warp] = sum;
    __syncthreads();
    sum = 0.f;
#pragma unroll
    for (int w2i = 0; w2i < 8; ++w2i) sum += red[w2i];
    float inv = 1.0f / sum;

    float* orow = g_probs + (size_t)bs * Ss;
    for (int i = tid; i < Ss; i += 256) orow[i] = lg[i] * inv;
}

// ====== tf32 tensor-core GEMM (R9 measured-best, unchanged) ======
template <int MODE>
__global__ __launch_bounds__(256) void gemm_mma(const float* __restrict__ Ap,
                                                const float* __restrict__ Bp,
                                                const float* __restrict__ Hjp,
                                                const float* __restrict__ bias,
                                                const float* __restrict__ alpha,
                                                float* __restrict__ Cp, int Kdim, int lda) {
    const int m0 = blockIdx.x * 128;
    const int n0 = blockIdx.y * 96;
    const float* A = Ap;
    const float* Bm = Bp;
    float* C = Cp;
    size_t rowbase = 0;
    if (MODE == 0) {
        int b = blockIdx.z;
        A += (size_t)b * Ss * Ss;
        Bm += (size_t)b * Ss * Hh;
        C += (size_t)b * Ss * Hh;
        rowbase = (size_t)b * Ss;
    }

    __shared__ unsigned As[2][128][20];
    __shared__ unsigned Bs[2][16][104];

    const int tid  = threadIdx.x;
    const int warp = tid >> 5, lane = tid & 31;
    const int g  = lane >> 2, t4 = lane & 3;
    const int wm = warp & 3;
    const int wn = warp >> 2;

    const int ar = tid >> 1, ac = (tid & 1) * 8;
    const int b0r = tid / 24, b0c = (tid % 24) * 4;
    const int i1  = tid + 256;
    const int b1r = i1 / 24, b1c = (i1 % 24) * 4;
    const bool hasB1 = (tid < 128);

    float acc[2][6][4];
#pragma unroll
    for (int mt = 0; mt < 2; ++mt)
#pragma unroll
        for (int nt = 0; nt < 6; ++nt)
#pragma unroll
            for (int v = 0; v < 4; ++v) acc[mt][nt][v] = 0.f;

    const int nkt = Kdim / 16;

    float4 pa0, pa1, pb0, pb1;

    auto loadAB = [&](int k0) {
        int kc = k0 + ac;
        if (MODE == 1) {
            int seg = kc / Hh;
            const float* base = (seg == 0) ? g_ctx : (seg == 1) ? Hjp : g_ctxh;
            int kq = kc - seg * Hh;
            pa0 = *(const float4*)(base + (size_t)(m0 + ar) * Hh + kq);
            pa1 = *(const float4*)(base + (size_t)(m0 + ar) * Hh + kq + 4);
        } else {
            pa0 = *(const float4*)(A + (size_t)(m0 + ar) * lda + kc);
            pa1 = *(const float4*)(A + (size_t)(m0 + ar) * lda + kc + 4);
        }
        pb0 = *(const float4*)(Bm + (size_t)(k0 + b0r) * Hh + n0 + b0c);
        if (hasB1) pb1 = *(const float4*)(Bm + (size_t)(k0 + b1r) * Hh + n0 + b1c);
    };

    auto storeAB = [&](int buf) {
        const float va[8] = {pa0.x, pa0.y, pa0.z, pa0.w, pa1.x, pa1.y, pa1.z, pa1.w};
#pragma unroll
        for (int j = 0; j < 8; ++j) As[buf][ar][ac + j] = tf32r(va[j]);
        const float w0[4] = {pb0.x, pb0.y, pb0.z, pb0.w};
#pragma unroll
        for (int j = 0; j < 4; ++j) Bs[buf][b0r][b0c + j] = tf32r(w0[j]);
        if (hasB1) {
            const float w1[4] = {pb1.x, pb1.y, pb1.z, pb1.w};
#pragma unroll
            for (int j = 0; j < 4; ++j) Bs[buf][b1r][b1c + j] = tf32r(w1[j]);
        }
    };

    loadAB(0);
    storeAB(0);
    __syncthreads();

#pragma unroll 1
    for (int kt = 0; kt < nkt; ++kt) {
        const int cur = kt & 1;
        const bool more = (kt + 1 < nkt);
        if (more) loadAB((kt + 1) * 16);

#pragma unroll
        for (int k8 = 0; k8 < 16; k8 += 8) {
            unsigned afr[2][4], bfr[6][2];
#pragma unroll
            for (int mt = 0; mt < 2; ++mt) {
                int rb = wm * 32 + mt * 16 + g;
                afr[mt][0] = As[cur][rb][k8 + t4];
                afr[mt][1] = As[cur][rb + 8][k8 + t4];
                afr[mt][2] = As[cur][rb][k8 + t4 + 4];
                afr[mt][3] = As[cur][rb + 8][k8 + t4 + 4];
            }
#pragma unroll
            for (int nt = 0; nt < 6; ++nt) {
                int cb = wn * 48 + nt * 8 + g;
                bfr[nt][0] = Bs[cur][k8 + t4][cb];
                bfr[nt][1] = Bs[cur][k8 + t4 + 4][cb];
            }
#pragma unroll
            for (int mt = 0; mt < 2; ++mt)
#pragma unroll
                for (int nt = 0; nt < 6; ++nt)
                    mma_tf32(acc[mt][nt][0], acc[mt][nt][1], acc[mt][nt][2], acc[mt][nt][3],
                             afr[mt][0], afr[mt][1], afr[mt][2], afr[mt][3],
                             bfr[nt][0], bfr[nt][1]);
        }
        if (more) {
            storeAB(cur ^ 1);
            __syncthreads();
        }
    }

    const float al = (MODE == 2) ? alpha[0] : 0.f;
#pragma unroll
    for (int mt = 0; mt < 2; ++mt) {
        int r0 = m0 + wm * 32 + mt * 16 + g;
        int r1 = r0 + 8;
#pragma unroll
        for (int nt = 0; nt < 6; ++nt) {
            int c0 = n0 + wn * 48 + nt * 8 + 2 * t4;
            float v00 = acc[mt][nt][0], v01 = acc[mt][nt][1];
            float v10 = acc[mt][nt][2], v11 = acc[mt][nt][3];
            if (MODE == 0) {
                *(float2*)(&C[(size_t)r0 * Hh + c0]) = make_float2(v00, v01);
                *(float2*)(&C[(size_t)r1 * Hh + c0]) = make_float2(v10, v11);
                size_t g0 = rowbase + r0, g1 = rowbase + r1;
                float2 h0 = *(const float2*)(Hjp + g0 * Hh + c0);
                float2 h1 = *(const float2*)(Hjp + g1 * Hh + c0);
                *(float2*)(&g_ctxh[g0 * Hh + c0]) = make_float2(v00 * h0.x, v01 * h0.y);
                *(float2*)(&g_ctxh[g1 * Hh + c0]) = make_float2(v10 * h1.x, v11 * h1.y);
            } else if (MODE == 1) {
                float2 bsv = *(const float2*)(&bias[c0]);
                *(float2*)(&C[(size_t)r0 * VHID + c0]) =
                    make_float2(fmaxf(v00 + bsv.x, 0.f), fmaxf(v01 + bsv.y, 0.f));
                *(float2*)(&C[(size_t)r1 * VHID + c0]) =
                    make_float2(fmaxf(v10 + bsv.x, 0.f), fmaxf(v11 + bsv.y, 0.f));
            } else {
                float2 bsv = *(const float2*)(&bias[c0]);
                *(float2*)(&C[(size_t)r0 * Hh + c0]) =
                    make_float2(al * (v00 + bsv.x), al * (v01 + bsv.y));
                *(float2*)(&C[(size_t)r1 * Hh + c0]) =
                    make_float2(al * (v10 + bsv.x), al * (v11 + bsv.y));
            }
        }
    }
}

// ================= launch =================
extern "C" void kernel_launch(void* const* d_in, const int* in_sizes, int n_in, void* d_out,
                              int out_size) {
    const float* Hj   = (const float*)d_in[0];
    const float* Hi   = (const float*)d_in[1];
    const float* mask = (const float*)d_in[2];
    const float* Wpj  = (const float*)d_in[3];
    const float* Wpi  = (const float*)d_in[4];
    const float* W1   = (const float*)d_in[5];
    const float* b1   = (const float*)d_in[6];
    const float* W2   = (const float*)d_in[7];
    // d_in[8] = b2: constant logit shift -> cancels in softmax
    const float* Wv1   = (const float*)d_in[9];
    const float* bv1   = (const float*)d_in[10];
    const float* Wv2   = (const float*)d_in[11];
    const float* bv2   = (const float*)d_in[12];
    const float* alpha = (const float*)d_in[13];
    float* out = (float*)d_out;

    float* d_probs = nullptr;
    float* d_ctx = nullptr;
    float* d_hid = nullptr;
    cudaGetSymbolAddress((void**)&d_probs, g_probs);
    cudaGetSymbolAddress((void**)&d_ctx, g_ctx);
    cudaGetSymbolAddress((void**)&d_hid, g_hid);

    k1_prep<<<Bb * Ss, 128>>>(Hj, Hi, Wpj, Wpi, W1, b1);
    k2_mma<<<Bb * Ss, 256>>>(W1, W2, mask);
    gemm_mma<0><<<dim3(Ss / 128, Hh / 96, Bb), 256>>>(d_probs, Hi, Hj, nullptr, nullptr,
                                                      d_ctx, Ss, Ss);
    gemm_mma<1><<<dim3(Bb * Ss / 128, VHID / 96), 256>>>(nullptr, Wv1, Hj, bv1, nullptr, d_hid,
                                                         VIN, 0);
    gemm_mma<2><<<dim3(Bb * Ss / 128, Hh / 96), 256>>>(d_hid, Wv2, nullptr, bv2, alpha, out,
                                                       VHID, VHID);
}